// round 12
// baseline (speedup 1.0000x reference)
#include <cuda_runtime.h>

// Problem constants (fixed by the dataset)
#define NMAX 50000
#define EMAX 640000
#define GRP 8
#define PERM 1000003LL   // prime > group count -> bijective permutation
#define SCAN_CHUNK 1024

// Scratch (allocation-free rule: __device__ globals)
__device__ int   g_count[NMAX];
__device__ float g_dinv[NMAX];
__device__ int   g_part[256];
__device__ int   g_cursor[NMAX];
__device__ int4  g_pack[EMAX];          // {src, dst, norm_bits, 0}, dst-sorted
__device__ float g_h[NMAX * 128];
__device__ float g_agg1[NMAX * 128];
__device__ float g_agg2[NMAX * 128];
__device__ float g_h3[NMAX * 40];

__device__ __forceinline__ void red4(float* p, float a, float b, float c, float d) {
    asm volatile("red.global.add.v4.f32 [%0], {%1, %2, %3, %4};"
                 :: "l"(p), "f"(a), "f"(b), "f"(c), "f"(d) : "memory");
}

// ---------------------------------------------------------------------------
// Preamble
// ---------------------------------------------------------------------------
__global__ void zero_kernel(int* count, float* deg, int n) {
    int i = blockIdx.x * blockDim.x + threadIdx.x;
    if (i < n) { count[i] = 0; deg[i] = 1.0f; }
}

__global__ void hist_kernel(const int* __restrict__ dst,
                            const float* __restrict__ ew,
                            int* __restrict__ count,
                            float* __restrict__ deg, int e) {
    int i = blockIdx.x * blockDim.x + threadIdx.x;
    if (i < e) {
        int d = dst[i];
        atomicAdd(count + d, 1);
        atomicAdd(deg + d, ew[i]);
    }
}

__global__ void __launch_bounds__(256)
partial_kernel(const int* __restrict__ count, int* __restrict__ part, int n) {
    const int t = threadIdx.x;
    const int base = blockIdx.x * SCAN_CHUNK + t * 4;
    int s = 0;
#pragma unroll
    for (int i = 0; i < 4; i++) {
        int idx = base + i;
        if (idx < n) s += count[idx];
    }
#pragma unroll
    for (int o = 16; o; o >>= 1) s += __shfl_down_sync(~0u, s, o);
    __shared__ int wsum[8];
    if ((t & 31) == 0) wsum[t >> 5] = s;
    __syncthreads();
    if (t == 0) {
        int v = 0;
#pragma unroll
        for (int i = 0; i < 8; i++) v += wsum[i];
        part[blockIdx.x] = v;
    }
}

__global__ void __launch_bounds__(256)
scanpart_kernel(int* __restrict__ part, int nb) {
    __shared__ int sh[256];
    const int t = threadIdx.x;
    int orig = (t < nb) ? part[t] : 0;
    sh[t] = orig;
    __syncthreads();
    for (int off = 1; off < 256; off <<= 1) {
        int v = (t >= off) ? sh[t - off] : 0;
        __syncthreads();
        sh[t] += v;
        __syncthreads();
    }
    if (t < nb) part[t] = sh[t] - orig;
}

__global__ void __launch_bounds__(256)
scanfinal_kernel(const int* __restrict__ count,
                 const int* __restrict__ part,
                 float* __restrict__ deg_dinv,
                 int* __restrict__ cursor, int n) {
    const int t = threadIdx.x;
    const int base = blockIdx.x * SCAN_CHUNK + t * 4;
    int c[4];
    int s = 0;
#pragma unroll
    for (int i = 0; i < 4; i++) {
        int idx = base + i;
        c[i] = (idx < n) ? count[idx] : 0;
        s += c[i];
    }
    int inc = s;
#pragma unroll
    for (int o = 1; o < 32; o <<= 1) {
        int v = __shfl_up_sync(~0u, inc, o);
        if ((t & 31) >= o) inc += v;
    }
    __shared__ int wtot[8], woff[8];
    if ((t & 31) == 31) wtot[t >> 5] = inc;
    __syncthreads();
    if (t == 0) {
        int run = 0;
#pragma unroll
        for (int i = 0; i < 8; i++) { woff[i] = run; run += wtot[i]; }
    }
    __syncthreads();
    int run = inc - s + woff[t >> 5] + part[blockIdx.x];
#pragma unroll
    for (int i = 0; i < 4; i++) {
        int idx = base + i;
        if (idx < n) {
            cursor[idx] = run;
            run += c[i];
            deg_dinv[idx] = rsqrtf(deg_dinv[idx]);
        }
    }
}

__global__ void fill_kernel(const int* __restrict__ src,
                            const int* __restrict__ dst,
                            const float* __restrict__ ew,
                            const float* __restrict__ dinv,
                            int* __restrict__ cursor,
                            int4* __restrict__ pack, int e) {
    int i = blockIdx.x * blockDim.x + threadIdx.x;
    if (i >= e) return;
    int s = src[i];
    int d = dst[i];
    int pos = atomicAdd(cursor + d, 1);
    int4 p;
    p.x = s;
    p.y = d;
    p.z = __float_as_int(dinv[s] * ew[i] * dinv[d]);
    p.w = 0;
    pack[pos] = p;
}

// agg = h*dinv^2 + bias (layer-1 epilogue)
__global__ void agg_init128(const float* __restrict__ h,
                            const float* __restrict__ dinv,
                            const float* __restrict__ bias,
                            float* __restrict__ agg, int n) {
    int idx = blockIdx.x * blockDim.x + threadIdx.x;
    if (idx >= n * 32) return;
    int row = idx >> 5;
    int c = idx & 31;
    float di = dinv[row];
    di *= di;
    float4 hv = ((const float4*)h)[idx];
    float4 bv = ((const float4*)bias)[c];
    ((float4*)agg)[idx] = make_float4(fmaf(hv.x, di, bv.x), fmaf(hv.y, di, bv.y),
                                      fmaf(hv.z, di, bv.z), fmaf(hv.w, di, bv.w));
}

// ---------------------------------------------------------------------------
// GEMM: [n,128] @ [128,128], double-buffered smem pipeline.
// ---------------------------------------------------------------------------
template <bool RELU_IN, bool FUSE_EPI>
__global__ void __launch_bounds__(256, 2)
gemm128_kernel(const float* __restrict__ A,
               const float* __restrict__ W,
               const float* __restrict__ bias,
               const float* __restrict__ dinv,
               float* __restrict__ Hout,
               float* __restrict__ AggOut,
               int n) {
    __shared__ float As[2][16][128];   // As[buf][k][m]
    __shared__ float Bs[2][16][128];   // Bs[buf][k][n]

    const int tid = threadIdx.x;
    const int tx = tid & 15;
    const int ty = tid >> 4;
    const int rb = blockIdx.x * 128;

    // loader mapping (per l in 0..1): f = tid + l*256
    const int fA_row[2] = { (tid + 0) >> 2, (tid + 256) >> 2 };
    const int fA_c4[2]  = { ((tid + 0) & 3) * 4, ((tid + 256) & 3) * 4 };
    const int fB_kr[2]  = { (tid + 0) >> 5, (tid + 256) >> 5 };
    const int fB_c[2]   = { ((tid + 0) & 31) * 4, ((tid + 256) & 31) * 4 };

    float4 pa[2], pb[2];

    // prefetch stage 0
#pragma unroll
    for (int l = 0; l < 2; l++) {
        float4 v = make_float4(0.f, 0.f, 0.f, 0.f);
        int gr = rb + fA_row[l];
        if (gr < n) v = *(const float4*)(A + (size_t)gr * 128 + fA_c4[l]);
        if (RELU_IN) {
            v.x = fmaxf(v.x, 0.f); v.y = fmaxf(v.y, 0.f);
            v.z = fmaxf(v.z, 0.f); v.w = fmaxf(v.w, 0.f);
        }
        pa[l] = v;
        pb[l] = *(const float4*)(W + (size_t)fB_kr[l] * 128 + fB_c[l]);
    }
#pragma unroll
    for (int l = 0; l < 2; l++) {
        As[0][fA_c4[l] + 0][fA_row[l]] = pa[l].x;
        As[0][fA_c4[l] + 1][fA_row[l]] = pa[l].y;
        As[0][fA_c4[l] + 2][fA_row[l]] = pa[l].z;
        As[0][fA_c4[l] + 3][fA_row[l]] = pa[l].w;
        *(float4*)&Bs[0][fB_kr[l]][fB_c[l]] = pb[l];
    }
    __syncthreads();

    float acc[8][8];
#pragma unroll
    for (int i = 0; i < 8; i++)
#pragma unroll
        for (int j = 0; j < 8; j++) acc[i][j] = 0.0f;

#pragma unroll
    for (int s = 0; s < 8; s++) {
        const int cur = s & 1;
        // issue loads for stage s+1 (latency hidden behind compute)
        if (s < 7) {
            int k0 = (s + 1) * 16;
#pragma unroll
            for (int l = 0; l < 2; l++) {
                float4 v = make_float4(0.f, 0.f, 0.f, 0.f);
                int gr = rb + fA_row[l];
                if (gr < n) v = *(const float4*)(A + (size_t)gr * 128 + k0 + fA_c4[l]);
                if (RELU_IN) {
                    v.x = fmaxf(v.x, 0.f); v.y = fmaxf(v.y, 0.f);
                    v.z = fmaxf(v.z, 0.f); v.w = fmaxf(v.w, 0.f);
                }
                pa[l] = v;
                pb[l] = *(const float4*)(W + (size_t)(k0 + fB_kr[l]) * 128 + fB_c[l]);
            }
        }

        // compute stage s
#pragma unroll
        for (int k = 0; k < 16; k++) {
            float4 a0 = *(const float4*)&As[cur][k][ty * 8];
            float4 a1 = *(const float4*)&As[cur][k][ty * 8 + 4];
            float4 b0 = *(const float4*)&Bs[cur][k][tx * 8];
            float4 b1 = *(const float4*)&Bs[cur][k][tx * 8 + 4];
            float a[8] = {a0.x, a0.y, a0.z, a0.w, a1.x, a1.y, a1.z, a1.w};
            float b[8] = {b0.x, b0.y, b0.z, b0.w, b1.x, b1.y, b1.z, b1.w};
#pragma unroll
            for (int i = 0; i < 8; i++)
#pragma unroll
                for (int j = 0; j < 8; j++)
                    acc[i][j] = fmaf(a[i], b[j], acc[i][j]);
        }

        if (s < 7) {
            const int nxt = cur ^ 1;
#pragma unroll
            for (int l = 0; l < 2; l++) {
                As[nxt][fA_c4[l] + 0][fA_row[l]] = pa[l].x;
                As[nxt][fA_c4[l] + 1][fA_row[l]] = pa[l].y;
                As[nxt][fA_c4[l] + 2][fA_row[l]] = pa[l].z;
                As[nxt][fA_c4[l] + 3][fA_row[l]] = pa[l].w;
                *(float4*)&Bs[nxt][fB_kr[l]][fB_c[l]] = pb[l];
            }
            __syncthreads();
        }
    }

#pragma unroll
    for (int i = 0; i < 8; i++) {
        int row = rb + ty * 8 + i;
        if (row >= n) break;
        float sl = 0.f;
        if (FUSE_EPI) { sl = dinv[row]; sl *= sl; }
#pragma unroll
        for (int j = 0; j < 8; j += 4) {
            int col = tx * 8 + j;
            float4 hv = make_float4(acc[i][j], acc[i][j + 1], acc[i][j + 2], acc[i][j + 3]);
            *(float4*)(Hout + (size_t)row * 128 + col) = hv;
            if (FUSE_EPI) {
                float4 bv = *(const float4*)(bias + col);
                float4 av;
                av.x = fmaf(hv.x, sl, bv.x);
                av.y = fmaf(hv.y, sl, bv.y);
                av.z = fmaf(hv.z, sl, bv.z);
                av.w = fmaf(hv.w, sl, bv.w);
                *(float4*)(AggOut + (size_t)row * 128 + col) = av;
            }
        }
    }
}

// ---------------------------------------------------------------------------
// Permuted segment-combining scatter (128 feats)
// ---------------------------------------------------------------------------
__global__ void __launch_bounds__(256)
scatter128_perm(const float* __restrict__ h,
                const int4* __restrict__ pack,
                float* __restrict__ agg, int e, int nw) {
    int w = (blockIdx.x * blockDim.x + threadIdx.x) >> 5;
    int lane = threadIdx.x & 31;
    if (w >= nw) return;
    w = (int)(((long long)w * PERM) % nw);   // decorrelate concurrent dsts
    int base = w * GRP;
    int cnt = min(GRP, e - base);

    int4 p[GRP];
#pragma unroll
    for (int g = 0; g < GRP; g++)
        if (g < cnt) p[g] = pack[base + g];

    float4 m[GRP];
#pragma unroll
    for (int g = 0; g < GRP; g++)
        if (g < cnt)
            m[g] = *(const float4*)(h + (size_t)p[g].x * 128 + lane * 4);

#pragma unroll
    for (int g = 0; g < GRP; g++)
        if (g < cnt) {
            float nm = __int_as_float(p[g].z);
            m[g].x *= nm; m[g].y *= nm; m[g].z *= nm; m[g].w *= nm;
        }

    float4 acc = m[0];
    int d = p[0].y;
#pragma unroll
    for (int g = 1; g < GRP; g++) {
        if (g < cnt) {
            if (p[g].y == d) {                 // warp-uniform branch
                acc.x += m[g].x; acc.y += m[g].y;
                acc.z += m[g].z; acc.w += m[g].w;
            } else {
                red4(agg + (size_t)d * 128 + lane * 4, acc.x, acc.y, acc.z, acc.w);
                acc = m[g];
                d = p[g].y;
            }
        }
    }
    red4(agg + (size_t)d * 128 + lane * 4, acc.x, acc.y, acc.z, acc.w);
}

// ---------------------------------------------------------------------------
// Layer-3 GEMM: relu(A)[n,128] @ [128,40] -> H3 and Out init
// ---------------------------------------------------------------------------
__global__ void __launch_bounds__(128)
gemm40_kernel(const float* __restrict__ A,
              const float* __restrict__ W,
              const float* __restrict__ bias,
              const float* __restrict__ dinv,
              float* __restrict__ Hout,
              float* __restrict__ Out,
              int n) {
    extern __shared__ float sm[];
    float* xs = sm;                 // 64 rows, stride 129
    float* ws = sm + 64 * 129;      // 128*40 flat

    const int tid = threadIdx.x;
    const int rb = blockIdx.x * 64;

    for (int l = tid * 4; l < 128 * 40; l += 128 * 4)
        *(float4*)(ws + l) = *(const float4*)(W + l);

    for (int f = tid; f < 2048; f += 128) {
        int row = f >> 5;
        int c = (f & 31) * 4;
        float4 v = make_float4(0.f, 0.f, 0.f, 0.f);
        int gr = rb + row;
        if (gr < n) v = *(const float4*)(A + (size_t)gr * 128 + c);
        float* xr = xs + row * 129 + c;
        xr[0] = fmaxf(v.x, 0.f);
        xr[1] = fmaxf(v.y, 0.f);
        xr[2] = fmaxf(v.z, 0.f);
        xr[3] = fmaxf(v.w, 0.f);
    }
    __syncthreads();

    const int tc = tid & 7;
    const int tr = tid >> 3;
    float acc[4][5];
#pragma unroll
    for (int r = 0; r < 4; r++)
#pragma unroll
        for (int j = 0; j < 5; j++) acc[r][j] = 0.0f;

#pragma unroll 4
    for (int k = 0; k < 128; k++) {
        float w[5];
#pragma unroll
        for (int j = 0; j < 5; j++) w[j] = ws[k * 40 + tc + 8 * j];
#pragma unroll
        for (int r = 0; r < 4; r++) {
            float a = xs[(tr * 4 + r) * 129 + k];
#pragma unroll
            for (int j = 0; j < 5; j++) acc[r][j] = fmaf(a, w[j], acc[r][j]);
        }
    }

#pragma unroll
    for (int r = 0; r < 4; r++) {
        int row = rb + tr * 4 + r;
        if (row >= n) break;
        float sl = dinv[row];
        sl = sl * sl;
#pragma unroll
        for (int j = 0; j < 5; j++) {
            int c = tc + 8 * j;
            float v = acc[r][j];
            Hout[(size_t)row * 40 + c] = v;
            Out[(size_t)row * 40 + c] = fmaf(v, sl, bias[c]);
        }
    }
}

// ---------------------------------------------------------------------------
// Permuted segment-combining scatter (40 feats): lanes 0..9 carry the row.
// ---------------------------------------------------------------------------
__global__ void __launch_bounds__(256)
scatter40_perm(const float* __restrict__ h,
               const int4* __restrict__ pack,
               float* __restrict__ out, int e, int nw) {
    int w = (blockIdx.x * blockDim.x + threadIdx.x) >> 5;
    int lane = threadIdx.x & 31;
    if (w >= nw) return;
    w = (int)(((long long)w * PERM) % nw);
    int base = w * GRP;
    int cnt = min(GRP, e - base);
    bool act = (lane < 10);

    int4 p[GRP];
#pragma unroll
    for (int g = 0; g < GRP; g++)
        if (g < cnt) p[g] = pack[base + g];

    float4 m[GRP];
#pragma unroll
    for (int g = 0; g < GRP; g++) {
        m[g] = make_float4(0.f, 0.f, 0.f, 0.f);
        if (g < cnt && act)
            m[g] = *(const float4*)(h + (size_t)p[g].x * 40 + lane * 4);
    }

#pragma unroll
    for (int g = 0; g < GRP; g++)
        if (g < cnt) {
            float nm = __int_as_float(p[g].z);
            m[g].x *= nm; m[g].y *= nm; m[g].z *= nm; m[g].w *= nm;
        }

    float4 acc = m[0];
    int d = p[0].y;
#pragma unroll
    for (int g = 1; g < GRP; g++) {
        if (g < cnt) {
            if (p[g].y == d) {
                acc.x += m[g].x; acc.y += m[g].y;
                acc.z += m[g].z; acc.w += m[g].w;
            } else {
                if (act)
                    red4(out + (size_t)d * 40 + lane * 4, acc.x, acc.y, acc.z, acc.w);
                acc = m[g];
                d = p[g].y;
            }
        }
    }
    if (act)
        red4(out + (size_t)d * 40 + lane * 4, acc.x, acc.y, acc.z, acc.w);
}

// ---------------------------------------------------------------------------
// Launch: gemm1 overlaps the graph preamble on a second stream.
// ---------------------------------------------------------------------------
extern "C" void kernel_launch(void* const* d_in, const int* in_sizes, int n_in,
                              void* d_out, int out_size) {
    const float* x  = (const float*)d_in[0];
    const int*   ei = (const int*)d_in[1];
    const float* ew = (const float*)d_in[2];
    const float* W1 = (const float*)d_in[3];
    const float* b1 = (const float*)d_in[4];
    const float* W2 = (const float*)d_in[5];
    const float* b2 = (const float*)d_in[6];
    const float* W3 = (const float*)d_in[7];
    const float* b3 = (const float*)d_in[8];
    float* out = (float*)d_out;

    const int n = in_sizes[0] / 128;       // 50000
    const int e = in_sizes[2];             // 640000
    const int* src = ei;
    const int* dst = ei + e;

    int *count, *cursor, *part;
    int4* pack;
    float *dinv, *h, *agg1, *agg2, *h3;
    cudaGetSymbolAddress((void**)&count,  g_count);
    cudaGetSymbolAddress((void**)&dinv,   g_dinv);
    cudaGetSymbolAddress((void**)&part,   g_part);
    cudaGetSymbolAddress((void**)&cursor, g_cursor);
    cudaGetSymbolAddress((void**)&pack,   g_pack);
    cudaGetSymbolAddress((void**)&h,      g_h);
    cudaGetSymbolAddress((void**)&agg1,   g_agg1);
    cudaGetSymbolAddress((void**)&agg2,   g_agg2);
    cudaGetSymbolAddress((void**)&h3,     g_h3);

    static cudaStream_t s2 = nullptr;
    static cudaEvent_t evFork = nullptr, evG1 = nullptr;
    if (s2 == nullptr) {
        cudaStreamCreateWithFlags(&s2, cudaStreamNonBlocking);
        cudaEventCreateWithFlags(&evFork, cudaEventDisableTiming);
        cudaEventCreateWithFlags(&evG1, cudaEventDisableTiming);
    }

    const int nb_n = (n + 255) / 256;
    const int nb_e = (e + 255) / 256;
    const int nb_scan = (n + SCAN_CHUNK - 1) / SCAN_CHUNK;   // 49
    const int gemm_blocks = (n + 127) / 128;
    const int nw = (e + GRP - 1) / GRP;
    const int scat_blocks = (nw * 32 + 255) / 256;

    // Fork: gemm1 (graph-independent, H only) on s2
    cudaEventRecord(evFork, 0);
    cudaStreamWaitEvent(s2, evFork, 0);
    gemm128_kernel<false, false><<<gemm_blocks, 256, 0, s2>>>(
        x, W1, nullptr, nullptr, h, nullptr, n);
    cudaEventRecord(evG1, s2);

    // Preamble on main stream (concurrent with gemm1)
    zero_kernel<<<nb_n, 256>>>(count, dinv, n);
    hist_kernel<<<nb_e, 256>>>(dst, ew, count, dinv, e);
    partial_kernel<<<nb_scan, 256>>>(count, part, n);
    scanpart_kernel<<<1, 256>>>(part, nb_scan);
    scanfinal_kernel<<<nb_scan, 256>>>(count, part, dinv, cursor, n);
    fill_kernel<<<nb_e, 256>>>(src, dst, ew, dinv, cursor, pack, e);

    // Join, then layer-1 epilogue + scatter
    cudaStreamWaitEvent(0, evG1, 0);
    agg_init128<<<(n * 32 + 255) / 256, 256>>>(h, dinv, b1, agg1, n);
    scatter128_perm<<<scat_blocks, 256>>>(h, pack, agg1, e, nw);

    // Layer 2 (relu + fused epilogue)
    gemm128_kernel<true, true><<<gemm_blocks, 256>>>(agg1, W2, b2, dinv, h, agg2, n);
    scatter128_perm<<<scat_blocks, 256>>>(h, pack, agg2, e, nw);

    // Layer 3 (relu fused; scatter straight to d_out)
    static const int g40_smem = (64 * 129 + 128 * 40) * sizeof(float);
    cudaFuncSetAttribute(gemm40_kernel,
                         cudaFuncAttributeMaxDynamicSharedMemorySize, g40_smem);
    gemm40_kernel<<<(n + 63) / 64, 128, g40_smem>>>(agg2, W3, b3, dinv, h3, out, n);
    scatter40_perm<<<scat_blocks, 256>>>(h3, pack, out, e, nw);
}

// round 13
// speedup vs baseline: 1.1512x; 1.1512x over previous
#include <cuda_runtime.h>

// Problem constants (fixed by the dataset)
#define NMAX 50000
#define EMAX 640000
#define GRP 8
#define PERM 1000003LL   // prime > group count -> bijective permutation
#define SCAN_CHUNK 1024

// Scratch (allocation-free rule: __device__ globals)
__device__ int   g_count[NMAX];
__device__ float g_dinv[NMAX];
__device__ int   g_part[256];
__device__ int   g_cursor[NMAX];
__device__ int4  g_pack[EMAX];          // {src, dst, norm_bits, 0}, dst-sorted
__device__ float g_h[NMAX * 128];
__device__ float g_agg1[NMAX * 128];
__device__ float g_agg2[NMAX * 128];
__device__ float g_h3[NMAX * 40];

__device__ __forceinline__ void red4(float* p, float a, float b, float c, float d) {
    asm volatile("red.global.add.v4.f32 [%0], {%1, %2, %3, %4};"
                 :: "l"(p), "f"(a), "f"(b), "f"(c), "f"(d) : "memory");
}

// ---------------------------------------------------------------------------
// Preamble
// ---------------------------------------------------------------------------
__global__ void zero_kernel(int* count, float* deg, int n) {
    int i = blockIdx.x * blockDim.x + threadIdx.x;
    if (i < n) { count[i] = 0; deg[i] = 1.0f; }
}

__global__ void hist_kernel(const int* __restrict__ dst,
                            const float* __restrict__ ew,
                            int* __restrict__ count,
                            float* __restrict__ deg, int e) {
    int i = blockIdx.x * blockDim.x + threadIdx.x;
    if (i < e) {
        int d = dst[i];
        atomicAdd(count + d, 1);
        atomicAdd(deg + d, ew[i]);
    }
}

__global__ void __launch_bounds__(256)
partial_kernel(const int* __restrict__ count, int* __restrict__ part, int n) {
    const int t = threadIdx.x;
    const int base = blockIdx.x * SCAN_CHUNK + t * 4;
    int s = 0;
#pragma unroll
    for (int i = 0; i < 4; i++) {
        int idx = base + i;
        if (idx < n) s += count[idx];
    }
#pragma unroll
    for (int o = 16; o; o >>= 1) s += __shfl_down_sync(~0u, s, o);
    __shared__ int wsum[8];
    if ((t & 31) == 0) wsum[t >> 5] = s;
    __syncthreads();
    if (t == 0) {
        int v = 0;
#pragma unroll
        for (int i = 0; i < 8; i++) v += wsum[i];
        part[blockIdx.x] = v;
    }
}

__global__ void __launch_bounds__(256)
scanpart_kernel(int* __restrict__ part, int nb) {
    __shared__ int sh[256];
    const int t = threadIdx.x;
    int orig = (t < nb) ? part[t] : 0;
    sh[t] = orig;
    __syncthreads();
    for (int off = 1; off < 256; off <<= 1) {
        int v = (t >= off) ? sh[t - off] : 0;
        __syncthreads();
        sh[t] += v;
        __syncthreads();
    }
    if (t < nb) part[t] = sh[t] - orig;
}

__global__ void __launch_bounds__(256)
scanfinal_kernel(const int* __restrict__ count,
                 const int* __restrict__ part,
                 float* __restrict__ deg_dinv,
                 int* __restrict__ cursor, int n) {
    const int t = threadIdx.x;
    const int base = blockIdx.x * SCAN_CHUNK + t * 4;
    int c[4];
    int s = 0;
#pragma unroll
    for (int i = 0; i < 4; i++) {
        int idx = base + i;
        c[i] = (idx < n) ? count[idx] : 0;
        s += c[i];
    }
    int inc = s;
#pragma unroll
    for (int o = 1; o < 32; o <<= 1) {
        int v = __shfl_up_sync(~0u, inc, o);
        if ((t & 31) >= o) inc += v;
    }
    __shared__ int wtot[8], woff[8];
    if ((t & 31) == 31) wtot[t >> 5] = inc;
    __syncthreads();
    if (t == 0) {
        int run = 0;
#pragma unroll
        for (int i = 0; i < 8; i++) { woff[i] = run; run += wtot[i]; }
    }
    __syncthreads();
    int run = inc - s + woff[t >> 5] + part[blockIdx.x];
#pragma unroll
    for (int i = 0; i < 4; i++) {
        int idx = base + i;
        if (idx < n) {
            cursor[idx] = run;
            run += c[i];
            deg_dinv[idx] = rsqrtf(deg_dinv[idx]);
        }
    }
}

__global__ void fill_kernel(const int* __restrict__ src,
                            const int* __restrict__ dst,
                            const float* __restrict__ ew,
                            const float* __restrict__ dinv,
                            int* __restrict__ cursor,
                            int4* __restrict__ pack, int e) {
    int i = blockIdx.x * blockDim.x + threadIdx.x;
    if (i >= e) return;
    int s = src[i];
    int d = dst[i];
    int pos = atomicAdd(cursor + d, 1);
    int4 p;
    p.x = s;
    p.y = d;
    p.z = __float_as_int(dinv[s] * ew[i] * dinv[d]);
    p.w = 0;
    pack[pos] = p;
}

// agg1 = bias broadcast (independent of graph/gemm -> runs in hidden preamble)
__global__ void init_bias128(float* __restrict__ out,
                             const float* __restrict__ bias, int n) {
    int idx = blockIdx.x * blockDim.x + threadIdx.x;   // float4 index
    if (idx < n * 32) {
        float4 bv = ((const float4*)bias)[idx & 31];
        ((float4*)out)[idx] = bv;
    }
}

// ---------------------------------------------------------------------------
// GEMM: [n,128] @ [128,128]. FUSE_EPI: also write Agg = H*dinv^2 + bias.
// (proven round-1/9 kernel, at the FFMA issue floor)
// ---------------------------------------------------------------------------
template <bool RELU_IN, bool FUSE_EPI>
__global__ void __launch_bounds__(256, 2)
gemm128_kernel(const float* __restrict__ A,
               const float* __restrict__ W,
               const float* __restrict__ bias,
               const float* __restrict__ dinv,
               float* __restrict__ Hout,
               float* __restrict__ AggOut,
               int n) {
    __shared__ float As[16][128];
    __shared__ float Bs[16][128];

    const int tid = threadIdx.x;
    const int tx = tid & 15;
    const int ty = tid >> 4;
    const int rb = blockIdx.x * 128;

    float acc[8][8];
#pragma unroll
    for (int i = 0; i < 8; i++)
#pragma unroll
        for (int j = 0; j < 8; j++) acc[i][j] = 0.0f;

    for (int k0 = 0; k0 < 128; k0 += 16) {
#pragma unroll
        for (int l = 0; l < 2; l++) {
            int f = tid + l * 256;
            int row = f >> 2;
            int c4 = (f & 3) * 4;
            float4 v = make_float4(0.f, 0.f, 0.f, 0.f);
            int gr = rb + row;
            if (gr < n) v = *(const float4*)(A + (size_t)gr * 128 + k0 + c4);
            if (RELU_IN) {
                v.x = fmaxf(v.x, 0.f); v.y = fmaxf(v.y, 0.f);
                v.z = fmaxf(v.z, 0.f); v.w = fmaxf(v.w, 0.f);
            }
            As[c4 + 0][row] = v.x;
            As[c4 + 1][row] = v.y;
            As[c4 + 2][row] = v.z;
            As[c4 + 3][row] = v.w;
        }
#pragma unroll
        for (int l = 0; l < 2; l++) {
            int f = tid + l * 256;
            int kr = f >> 5;
            int c = (f & 31) * 4;
            *(float4*)&Bs[kr][c] = *(const float4*)(W + (size_t)(k0 + kr) * 128 + c);
        }
        __syncthreads();

#pragma unroll
        for (int k = 0; k < 16; k++) {
            float4 a0 = *(const float4*)&As[k][ty * 8];
            float4 a1 = *(const float4*)&As[k][ty * 8 + 4];
            float4 b0 = *(const float4*)&Bs[k][tx * 8];
            float4 b1 = *(const float4*)&Bs[k][tx * 8 + 4];
            float a[8] = {a0.x, a0.y, a0.z, a0.w, a1.x, a1.y, a1.z, a1.w};
            float b[8] = {b0.x, b0.y, b0.z, b0.w, b1.x, b1.y, b1.z, b1.w};
#pragma unroll
            for (int i = 0; i < 8; i++)
#pragma unroll
                for (int j = 0; j < 8; j++)
                    acc[i][j] = fmaf(a[i], b[j], acc[i][j]);
        }
        __syncthreads();
    }

#pragma unroll
    for (int i = 0; i < 8; i++) {
        int row = rb + ty * 8 + i;
        if (row >= n) break;
        float sl = 0.f;
        if (FUSE_EPI) { sl = dinv[row]; sl *= sl; }
#pragma unroll
        for (int j = 0; j < 8; j += 4) {
            int col = tx * 8 + j;
            float4 hv = make_float4(acc[i][j], acc[i][j + 1], acc[i][j + 2], acc[i][j + 3]);
            *(float4*)(Hout + (size_t)row * 128 + col) = hv;
            if (FUSE_EPI) {
                float4 bv = *(const float4*)(bias + col);
                float4 av;
                av.x = fmaf(hv.x, sl, bv.x);
                av.y = fmaf(hv.y, sl, bv.y);
                av.z = fmaf(hv.z, sl, bv.z);
                av.w = fmaf(hv.w, sl, bv.w);
                *(float4*)(AggOut + (size_t)row * 128 + col) = av;
            }
        }
    }
}

// ---------------------------------------------------------------------------
// Permuted segment-combining scatter (128 feats).
// SELF: warps beyond the edge range also red the self-loop term h[v]*dinv^2
// (layer 1 only; layers 2/3 fuse it in the GEMM epilogue). One launch, one
// red storm, no serial epilogue kernel.
// ---------------------------------------------------------------------------
template <bool SELF>
__global__ void __launch_bounds__(256)
scatter128_perm(const float* __restrict__ h,
                const int4* __restrict__ pack,
                const float* __restrict__ dinv,
                float* __restrict__ agg, int e, int nw, int n) {
    int w = (blockIdx.x * blockDim.x + threadIdx.x) >> 5;
    int lane = threadIdx.x & 31;

    if (w >= nw) {
        if (SELF) {
            int v = w - nw;
            if (v < n) {
                float4 hv = *(const float4*)(h + (size_t)v * 128 + lane * 4);
                float di = dinv[v];
                di *= di;
                red4(agg + (size_t)v * 128 + lane * 4,
                     hv.x * di, hv.y * di, hv.z * di, hv.w * di);
            }
        }
        return;
    }
    w = (int)(((long long)w * PERM) % nw);   // decorrelate concurrent dsts
    int base = w * GRP;
    int cnt = min(GRP, e - base);

    int4 p[GRP];
#pragma unroll
    for (int g = 0; g < GRP; g++)
        if (g < cnt) p[g] = pack[base + g];

    float4 m[GRP];
#pragma unroll
    for (int g = 0; g < GRP; g++)
        if (g < cnt)
            m[g] = *(const float4*)(h + (size_t)p[g].x * 128 + lane * 4);

#pragma unroll
    for (int g = 0; g < GRP; g++)
        if (g < cnt) {
            float nm = __int_as_float(p[g].z);
            m[g].x *= nm; m[g].y *= nm; m[g].z *= nm; m[g].w *= nm;
        }

    float4 acc = m[0];
    int d = p[0].y;
#pragma unroll
    for (int g = 1; g < GRP; g++) {
        if (g < cnt) {
            if (p[g].y == d) {                 // warp-uniform branch
                acc.x += m[g].x; acc.y += m[g].y;
                acc.z += m[g].z; acc.w += m[g].w;
            } else {
                red4(agg + (size_t)d * 128 + lane * 4, acc.x, acc.y, acc.z, acc.w);
                acc = m[g];
                d = p[g].y;
            }
        }
    }
    red4(agg + (size_t)d * 128 + lane * 4, acc.x, acc.y, acc.z, acc.w);
}

// ---------------------------------------------------------------------------
// Layer-3 GEMM: relu(A)[n,128] @ [128,40] -> H3 and Out init
// ---------------------------------------------------------------------------
__global__ void __launch_bounds__(128)
gemm40_kernel(const float* __restrict__ A,
              const float* __restrict__ W,
              const float* __restrict__ bias,
              const float* __restrict__ dinv,
              float* __restrict__ Hout,
              float* __restrict__ Out,
              int n) {
    extern __shared__ float sm[];
    float* xs = sm;                 // 64 rows, stride 129
    float* ws = sm + 64 * 129;      // 128*40 flat

    const int tid = threadIdx.x;
    const int rb = blockIdx.x * 64;

    for (int l = tid * 4; l < 128 * 40; l += 128 * 4)
        *(float4*)(ws + l) = *(const float4*)(W + l);

    for (int f = tid; f < 2048; f += 128) {
        int row = f >> 5;
        int c = (f & 31) * 4;
        float4 v = make_float4(0.f, 0.f, 0.f, 0.f);
        int gr = rb + row;
        if (gr < n) v = *(const float4*)(A + (size_t)gr * 128 + c);
        float* xr = xs + row * 129 + c;
        xr[0] = fmaxf(v.x, 0.f);
        xr[1] = fmaxf(v.y, 0.f);
        xr[2] = fmaxf(v.z, 0.f);
        xr[3] = fmaxf(v.w, 0.f);
    }
    __syncthreads();

    const int tc = tid & 7;
    const int tr = tid >> 3;
    float acc[4][5];
#pragma unroll
    for (int r = 0; r < 4; r++)
#pragma unroll
        for (int j = 0; j < 5; j++) acc[r][j] = 0.0f;

#pragma unroll 4
    for (int k = 0; k < 128; k++) {
        float w[5];
#pragma unroll
        for (int j = 0; j < 5; j++) w[j] = ws[k * 40 + tc + 8 * j];
#pragma unroll
        for (int r = 0; r < 4; r++) {
            float a = xs[(tr * 4 + r) * 129 + k];
#pragma unroll
            for (int j = 0; j < 5; j++) acc[r][j] = fmaf(a, w[j], acc[r][j]);
        }
    }

#pragma unroll
    for (int r = 0; r < 4; r++) {
        int row = rb + tr * 4 + r;
        if (row >= n) break;
        float sl = dinv[row];
        sl = sl * sl;
#pragma unroll
        for (int j = 0; j < 5; j++) {
            int c = tc + 8 * j;
            float v = acc[r][j];
            Hout[(size_t)row * 40 + c] = v;
            Out[(size_t)row * 40 + c] = fmaf(v, sl, bias[c]);
        }
    }
}

// ---------------------------------------------------------------------------
// Permuted segment-combining scatter (40 feats): lanes 0..9 carry the row.
// ---------------------------------------------------------------------------
__global__ void __launch_bounds__(256)
scatter40_perm(const float* __restrict__ h,
               const int4* __restrict__ pack,
               float* __restrict__ out, int e, int nw) {
    int w = (blockIdx.x * blockDim.x + threadIdx.x) >> 5;
    int lane = threadIdx.x & 31;
    if (w >= nw) return;
    w = (int)(((long long)w * PERM) % nw);
    int base = w * GRP;
    int cnt = min(GRP, e - base);
    bool act = (lane < 10);

    int4 p[GRP];
#pragma unroll
    for (int g = 0; g < GRP; g++)
        if (g < cnt) p[g] = pack[base + g];

    float4 m[GRP];
#pragma unroll
    for (int g = 0; g < GRP; g++) {
        m[g] = make_float4(0.f, 0.f, 0.f, 0.f);
        if (g < cnt && act)
            m[g] = *(const float4*)(h + (size_t)p[g].x * 40 + lane * 4);
    }

#pragma unroll
    for (int g = 0; g < GRP; g++)
        if (g < cnt) {
            float nm = __int_as_float(p[g].z);
            m[g].x *= nm; m[g].y *= nm; m[g].z *= nm; m[g].w *= nm;
        }

    float4 acc = m[0];
    int d = p[0].y;
#pragma unroll
    for (int g = 1; g < GRP; g++) {
        if (g < cnt) {
            if (p[g].y == d) {
                acc.x += m[g].x; acc.y += m[g].y;
                acc.z += m[g].z; acc.w += m[g].w;
            } else {
                if (act)
                    red4(out + (size_t)d * 40 + lane * 4, acc.x, acc.y, acc.z, acc.w);
                acc = m[g];
                d = p[g].y;
            }
        }
    }
    if (act)
        red4(out + (size_t)d * 40 + lane * 4, acc.x, acc.y, acc.z, acc.w);
}

// ---------------------------------------------------------------------------
// Launch: gemm1 overlaps the graph preamble on a second stream.
// ---------------------------------------------------------------------------
extern "C" void kernel_launch(void* const* d_in, const int* in_sizes, int n_in,
                              void* d_out, int out_size) {
    const float* x  = (const float*)d_in[0];
    const int*   ei = (const int*)d_in[1];
    const float* ew = (const float*)d_in[2];
    const float* W1 = (const float*)d_in[3];
    const float* b1 = (const float*)d_in[4];
    const float* W2 = (const float*)d_in[5];
    const float* b2 = (const float*)d_in[6];
    const float* W3 = (const float*)d_in[7];
    const float* b3 = (const float*)d_in[8];
    float* out = (float*)d_out;

    const int n = in_sizes[0] / 128;       // 50000
    const int e = in_sizes[2];             // 640000
    const int* src = ei;
    const int* dst = ei + e;

    int *count, *cursor, *part;
    int4* pack;
    float *dinv, *h, *agg1, *agg2, *h3;
    cudaGetSymbolAddress((void**)&count,  g_count);
    cudaGetSymbolAddress((void**)&dinv,   g_dinv);
    cudaGetSymbolAddress((void**)&part,   g_part);
    cudaGetSymbolAddress((void**)&cursor, g_cursor);
    cudaGetSymbolAddress((void**)&pack,   g_pack);
    cudaGetSymbolAddress((void**)&h,      g_h);
    cudaGetSymbolAddress((void**)&agg1,   g_agg1);
    cudaGetSymbolAddress((void**)&agg2,   g_agg2);
    cudaGetSymbolAddress((void**)&h3,     g_h3);

    static cudaStream_t s2 = nullptr;
    static cudaEvent_t evFork = nullptr, evG1 = nullptr;
    if (s2 == nullptr) {
        cudaStreamCreateWithFlags(&s2, cudaStreamNonBlocking);
        cudaEventCreateWithFlags(&evFork, cudaEventDisableTiming);
        cudaEventCreateWithFlags(&evG1, cudaEventDisableTiming);
    }

    const int nb_n = (n + 255) / 256;
    const int nb_e = (e + 255) / 256;
    const int nb_scan = (n + SCAN_CHUNK - 1) / SCAN_CHUNK;   // 49
    const int gemm_blocks = (n + 127) / 128;
    const int nw = (e + GRP - 1) / GRP;
    const int scat_blocks = (nw * 32 + 255) / 256;
    const int scat_self_blocks = ((nw + n) * 32 + 255) / 256;  // edge + self warps

    // Fork: gemm1 (graph-independent, H only) on s2
    cudaEventRecord(evFork, 0);
    cudaStreamWaitEvent(s2, evFork, 0);
    gemm128_kernel<false, false><<<gemm_blocks, 256, 0, s2>>>(
        x, W1, nullptr, nullptr, h, nullptr, n);
    cudaEventRecord(evG1, s2);

    // Preamble on main stream (concurrent with gemm1)
    zero_kernel<<<nb_n, 256>>>(count, dinv, n);
    init_bias128<<<(n * 32 + 255) / 256, 256>>>(agg1, b1, n);   // agg1 = b1
    hist_kernel<<<nb_e, 256>>>(dst, ew, count, dinv, e);
    partial_kernel<<<nb_scan, 256>>>(count, part, n);
    scanpart_kernel<<<1, 256>>>(part, nb_scan);
    scanfinal_kernel<<<nb_scan, 256>>>(count, part, dinv, cursor, n);
    fill_kernel<<<nb_e, 256>>>(src, dst, ew, dinv, cursor, pack, e);

    // Join, then layer-1 scatter (edges + self-loop in ONE launch)
    cudaStreamWaitEvent(0, evG1, 0);
    scatter128_perm<true><<<scat_self_blocks, 256>>>(h, pack, dinv, agg1, e, nw, n);

    // Layer 2 (relu + fused store epilogue)
    gemm128_kernel<true, true><<<gemm_blocks, 256>>>(agg1, W2, b2, dinv, h, agg2, n);
    scatter128_perm<false><<<scat_blocks, 256>>>(h, pack, dinv, agg2, e, nw, n);

    // Layer 3 (relu fused; scatter straight to d_out)
    static const int g40_smem = (64 * 129 + 128 * 40) * sizeof(float);
    cudaFuncSetAttribute(gemm40_kernel,
                         cudaFuncAttributeMaxDynamicSharedMemorySize, g40_smem);
    gemm40_kernel<<<(n + 63) / 64, 128, g40_smem>>>(agg2, W3, b3, dinv, h3, out, n);
    scatter40_perm<<<scat_blocks, 256>>>(h3, pack, out, e, nw);
}

// round 14
// speedup vs baseline: 1.3561x; 1.1780x over previous
#include <cuda_runtime.h>

// Problem constants (fixed by the dataset)
#define NMAX 50000
#define EMAX 640000
#define GRP 8
#define PERM 1000003LL   // prime > group count -> bijective permutation
#define SCAN_CHUNK 1024

// Scratch (allocation-free rule: __device__ globals)
__device__ int   g_count[NMAX];
__device__ float g_dinv[NMAX];
__device__ int   g_part[256];
__device__ int   g_cursor[NMAX];
__device__ int4  g_pack[EMAX];          // {src, dst, norm_bits, 0}, dst-sorted
__device__ float g_h[NMAX * 128];
__device__ float g_agg1[NMAX * 128];
__device__ float g_agg2[NMAX * 128];
__device__ float g_h3[NMAX * 40];

__device__ __forceinline__ void red4(float* p, float a, float b, float c, float d) {
    asm volatile("red.global.add.v4.f32 [%0], {%1, %2, %3, %4};"
                 :: "l"(p), "f"(a), "f"(b), "f"(c), "f"(d) : "memory");
}

// ---------------------------------------------------------------------------
// Preamble
// ---------------------------------------------------------------------------
__global__ void zero_kernel(int* count, float* deg, int n) {
    int i = blockIdx.x * blockDim.x + threadIdx.x;
    if (i < n) { count[i] = 0; deg[i] = 1.0f; }
}

__global__ void hist_kernel(const int* __restrict__ dst,
                            const float* __restrict__ ew,
                            int* __restrict__ count,
                            float* __restrict__ deg, int e) {
    int i = blockIdx.x * blockDim.x + threadIdx.x;
    if (i < e) {
        int d = dst[i];
        atomicAdd(count + d, 1);
        atomicAdd(deg + d, ew[i]);
    }
}

__global__ void __launch_bounds__(256)
partial_kernel(const int* __restrict__ count, int* __restrict__ part, int n) {
    const int t = threadIdx.x;
    const int base = blockIdx.x * SCAN_CHUNK + t * 4;
    int s = 0;
#pragma unroll
    for (int i = 0; i < 4; i++) {
        int idx = base + i;
        if (idx < n) s += count[idx];
    }
#pragma unroll
    for (int o = 16; o; o >>= 1) s += __shfl_down_sync(~0u, s, o);
    __shared__ int wsum[8];
    if ((t & 31) == 0) wsum[t >> 5] = s;
    __syncthreads();
    if (t == 0) {
        int v = 0;
#pragma unroll
        for (int i = 0; i < 8; i++) v += wsum[i];
        part[blockIdx.x] = v;
    }
}

__global__ void __launch_bounds__(256)
scanpart_kernel(int* __restrict__ part, int nb) {
    __shared__ int sh[256];
    const int t = threadIdx.x;
    int orig = (t < nb) ? part[t] : 0;
    sh[t] = orig;
    __syncthreads();
    for (int off = 1; off < 256; off <<= 1) {
        int v = (t >= off) ? sh[t - off] : 0;
        __syncthreads();
        sh[t] += v;
        __syncthreads();
    }
    if (t < nb) part[t] = sh[t] - orig;
}

__global__ void __launch_bounds__(256)
scanfinal_kernel(const int* __restrict__ count,
                 const int* __restrict__ part,
                 float* __restrict__ deg_dinv,
                 int* __restrict__ cursor, int n) {
    const int t = threadIdx.x;
    const int base = blockIdx.x * SCAN_CHUNK + t * 4;
    int c[4];
    int s = 0;
#pragma unroll
    for (int i = 0; i < 4; i++) {
        int idx = base + i;
        c[i] = (idx < n) ? count[idx] : 0;
        s += c[i];
    }
    int inc = s;
#pragma unroll
    for (int o = 1; o < 32; o <<= 1) {
        int v = __shfl_up_sync(~0u, inc, o);
        if ((t & 31) >= o) inc += v;
    }
    __shared__ int wtot[8], woff[8];
    if ((t & 31) == 31) wtot[t >> 5] = inc;
    __syncthreads();
    if (t == 0) {
        int run = 0;
#pragma unroll
        for (int i = 0; i < 8; i++) { woff[i] = run; run += wtot[i]; }
    }
    __syncthreads();
    int run = inc - s + woff[t >> 5] + part[blockIdx.x];
#pragma unroll
    for (int i = 0; i < 4; i++) {
        int idx = base + i;
        if (idx < n) {
            cursor[idx] = run;
            run += c[i];
            deg_dinv[idx] = rsqrtf(deg_dinv[idx]);
        }
    }
}

__global__ void fill_kernel(const int* __restrict__ src,
                            const int* __restrict__ dst,
                            const float* __restrict__ ew,
                            const float* __restrict__ dinv,
                            int* __restrict__ cursor,
                            int4* __restrict__ pack, int e) {
    int i = blockIdx.x * blockDim.x + threadIdx.x;
    if (i >= e) return;
    int s = src[i];
    int d = dst[i];
    int pos = atomicAdd(cursor + d, 1);
    int4 p;
    p.x = s;
    p.y = d;
    p.z = __float_as_int(dinv[s] * ew[i] * dinv[d]);
    p.w = 0;
    pack[pos] = p;
}

// agg = h*dinv^2 + bias (layer-1 epilogue)
__global__ void agg_init128(const float* __restrict__ h,
                            const float* __restrict__ dinv,
                            const float* __restrict__ bias,
                            float* __restrict__ agg, int n) {
    int idx = blockIdx.x * blockDim.x + threadIdx.x;
    if (idx >= n * 32) return;
    int row = idx >> 5;
    int c = idx & 31;
    float di = dinv[row];
    di *= di;
    float4 hv = ((const float4*)h)[idx];
    float4 bv = ((const float4*)bias)[c];
    ((float4*)agg)[idx] = make_float4(fmaf(hv.x, di, bv.x), fmaf(hv.y, di, bv.y),
                                      fmaf(hv.z, di, bv.z), fmaf(hv.w, di, bv.w));
}

// ---------------------------------------------------------------------------
// GEMM: [n,128] @ [128,128]. FUSE_EPI: also write Agg = H*dinv^2 + bias.
// (proven kernel, at the FFMA issue floor)
// ---------------------------------------------------------------------------
template <bool RELU_IN, bool FUSE_EPI>
__global__ void __launch_bounds__(256, 2)
gemm128_kernel(const float* __restrict__ A,
               const float* __restrict__ W,
               const float* __restrict__ bias,
               const float* __restrict__ dinv,
               float* __restrict__ Hout,
               float* __restrict__ AggOut,
               int n) {
    __shared__ float As[16][128];
    __shared__ float Bs[16][128];

    const int tid = threadIdx.x;
    const int tx = tid & 15;
    const int ty = tid >> 4;
    const int rb = blockIdx.x * 128;

    float acc[8][8];
#pragma unroll
    for (int i = 0; i < 8; i++)
#pragma unroll
        for (int j = 0; j < 8; j++) acc[i][j] = 0.0f;

    for (int k0 = 0; k0 < 128; k0 += 16) {
#pragma unroll
        for (int l = 0; l < 2; l++) {
            int f = tid + l * 256;
            int row = f >> 2;
            int c4 = (f & 3) * 4;
            float4 v = make_float4(0.f, 0.f, 0.f, 0.f);
            int gr = rb + row;
            if (gr < n) v = *(const float4*)(A + (size_t)gr * 128 + k0 + c4);
            if (RELU_IN) {
                v.x = fmaxf(v.x, 0.f); v.y = fmaxf(v.y, 0.f);
                v.z = fmaxf(v.z, 0.f); v.w = fmaxf(v.w, 0.f);
            }
            As[c4 + 0][row] = v.x;
            As[c4 + 1][row] = v.y;
            As[c4 + 2][row] = v.z;
            As[c4 + 3][row] = v.w;
        }
#pragma unroll
        for (int l = 0; l < 2; l++) {
            int f = tid + l * 256;
            int kr = f >> 5;
            int c = (f & 31) * 4;
            *(float4*)&Bs[kr][c] = *(const float4*)(W + (size_t)(k0 + kr) * 128 + c);
        }
        __syncthreads();

#pragma unroll
        for (int k = 0; k < 16; k++) {
            float4 a0 = *(const float4*)&As[k][ty * 8];
            float4 a1 = *(const float4*)&As[k][ty * 8 + 4];
            float4 b0 = *(const float4*)&Bs[k][tx * 8];
            float4 b1 = *(const float4*)&Bs[k][tx * 8 + 4];
            float a[8] = {a0.x, a0.y, a0.z, a0.w, a1.x, a1.y, a1.z, a1.w};
            float b[8] = {b0.x, b0.y, b0.z, b0.w, b1.x, b1.y, b1.z, b1.w};
#pragma unroll
            for (int i = 0; i < 8; i++)
#pragma unroll
                for (int j = 0; j < 8; j++)
                    acc[i][j] = fmaf(a[i], b[j], acc[i][j]);
        }
        __syncthreads();
    }

#pragma unroll
    for (int i = 0; i < 8; i++) {
        int row = rb + ty * 8 + i;
        if (row >= n) break;
        float sl = 0.f;
        if (FUSE_EPI) { sl = dinv[row]; sl *= sl; }
#pragma unroll
        for (int j = 0; j < 8; j += 4) {
            int col = tx * 8 + j;
            float4 hv = make_float4(acc[i][j], acc[i][j + 1], acc[i][j + 2], acc[i][j + 3]);
            *(float4*)(Hout + (size_t)row * 128 + col) = hv;
            if (FUSE_EPI) {
                float4 bv = *(const float4*)(bias + col);
                float4 av;
                av.x = fmaf(hv.x, sl, bv.x);
                av.y = fmaf(hv.y, sl, bv.y);
                av.z = fmaf(hv.z, sl, bv.z);
                av.w = fmaf(hv.w, sl, bv.w);
                *(float4*)(AggOut + (size_t)row * 128 + col) = av;
            }
        }
    }
}

// ---------------------------------------------------------------------------
// Permuted segment-combining scatter (128 feats), BATCHED (4-wide live set):
// halves register pressure vs the 8-wide version -> ~2x resident CTAs/SM,
// covering the exposed L2 gather latency. Combining state (acc,d) carries
// across batches, so red count is unchanged.
// ---------------------------------------------------------------------------
__global__ void __launch_bounds__(256)
scatter128_perm(const float* __restrict__ h,
                const int4* __restrict__ pack,
                float* __restrict__ agg, int e, int nw) {
    int w = (blockIdx.x * blockDim.x + threadIdx.x) >> 5;
    int lane = threadIdx.x & 31;
    if (w >= nw) return;
    w = (int)(((long long)w * PERM) % nw);   // decorrelate concurrent dsts
    int base = w * GRP;
    int cnt = min(GRP, e - base);

    float4 acc = make_float4(0.f, 0.f, 0.f, 0.f);
    int d = -1;

#pragma unroll
    for (int b = 0; b < GRP / 4; b++) {
        int4 p[4];
#pragma unroll
        for (int g = 0; g < 4; g++) {
            int i = b * 4 + g;
            if (i < cnt) p[g] = pack[base + i];
        }
        float4 m[4];
#pragma unroll
        for (int g = 0; g < 4; g++) {
            int i = b * 4 + g;
            if (i < cnt)
                m[g] = *(const float4*)(h + (size_t)p[g].x * 128 + lane * 4);
        }
#pragma unroll
        for (int g = 0; g < 4; g++) {
            int i = b * 4 + g;
            if (i < cnt) {
                float nm = __int_as_float(p[g].z);
                m[g].x *= nm; m[g].y *= nm; m[g].z *= nm; m[g].w *= nm;
            }
        }
#pragma unroll
        for (int g = 0; g < 4; g++) {
            int i = b * 4 + g;
            if (i < cnt) {
                if (i == 0) {
                    acc = m[0];
                    d = p[0].y;
                } else if (p[g].y == d) {       // warp-uniform branch
                    acc.x += m[g].x; acc.y += m[g].y;
                    acc.z += m[g].z; acc.w += m[g].w;
                } else {
                    red4(agg + (size_t)d * 128 + lane * 4, acc.x, acc.y, acc.z, acc.w);
                    acc = m[g];
                    d = p[g].y;
                }
            }
        }
    }
    red4(agg + (size_t)d * 128 + lane * 4, acc.x, acc.y, acc.z, acc.w);
}

// ---------------------------------------------------------------------------
// Layer-3 GEMM: relu(A)[n,128] @ [128,40] -> H3 and Out init
// ---------------------------------------------------------------------------
__global__ void __launch_bounds__(128)
gemm40_kernel(const float* __restrict__ A,
              const float* __restrict__ W,
              const float* __restrict__ bias,
              const float* __restrict__ dinv,
              float* __restrict__ Hout,
              float* __restrict__ Out,
              int n) {
    extern __shared__ float sm[];
    float* xs = sm;                 // 64 rows, stride 129
    float* ws = sm + 64 * 129;      // 128*40 flat

    const int tid = threadIdx.x;
    const int rb = blockIdx.x * 64;

    for (int l = tid * 4; l < 128 * 40; l += 128 * 4)
        *(float4*)(ws + l) = *(const float4*)(W + l);

    for (int f = tid; f < 2048; f += 128) {
        int row = f >> 5;
        int c = (f & 31) * 4;
        float4 v = make_float4(0.f, 0.f, 0.f, 0.f);
        int gr = rb + row;
        if (gr < n) v = *(const float4*)(A + (size_t)gr * 128 + c);
        float* xr = xs + row * 129 + c;
        xr[0] = fmaxf(v.x, 0.f);
        xr[1] = fmaxf(v.y, 0.f);
        xr[2] = fmaxf(v.z, 0.f);
        xr[3] = fmaxf(v.w, 0.f);
    }
    __syncthreads();

    const int tc = tid & 7;
    const int tr = tid >> 3;
    float acc[4][5];
#pragma unroll
    for (int r = 0; r < 4; r++)
#pragma unroll
        for (int j = 0; j < 5; j++) acc[r][j] = 0.0f;

#pragma unroll 4
    for (int k = 0; k < 128; k++) {
        float w[5];
#pragma unroll
        for (int j = 0; j < 5; j++) w[j] = ws[k * 40 + tc + 8 * j];
#pragma unroll
        for (int r = 0; r < 4; r++) {
            float a = xs[(tr * 4 + r) * 129 + k];
#pragma unroll
            for (int j = 0; j < 5; j++) acc[r][j] = fmaf(a, w[j], acc[r][j]);
        }
    }

#pragma unroll
    for (int r = 0; r < 4; r++) {
        int row = rb + tr * 4 + r;
        if (row >= n) break;
        float sl = dinv[row];
        sl = sl * sl;
#pragma unroll
        for (int j = 0; j < 5; j++) {
            int c = tc + 8 * j;
            float v = acc[r][j];
            Hout[(size_t)row * 40 + c] = v;
            Out[(size_t)row * 40 + c] = fmaf(v, sl, bias[c]);
        }
    }
}

// ---------------------------------------------------------------------------
// Permuted segment-combining scatter (40 feats), BATCHED; lanes 0..9 active.
// ---------------------------------------------------------------------------
__global__ void __launch_bounds__(256)
scatter40_perm(const float* __restrict__ h,
               const int4* __restrict__ pack,
               float* __restrict__ out, int e, int nw) {
    int w = (blockIdx.x * blockDim.x + threadIdx.x) >> 5;
    int lane = threadIdx.x & 31;
    if (w >= nw) return;
    w = (int)(((long long)w * PERM) % nw);
    int base = w * GRP;
    int cnt = min(GRP, e - base);
    bool act = (lane < 10);

    float4 acc = make_float4(0.f, 0.f, 0.f, 0.f);
    int d = -1;

#pragma unroll
    for (int b = 0; b < GRP / 4; b++) {
        int4 p[4];
#pragma unroll
        for (int g = 0; g < 4; g++) {
            int i = b * 4 + g;
            if (i < cnt) p[g] = pack[base + i];
        }
        float4 m[4];
#pragma unroll
        for (int g = 0; g < 4; g++) {
            int i = b * 4 + g;
            m[g] = make_float4(0.f, 0.f, 0.f, 0.f);
            if (i < cnt && act)
                m[g] = *(const float4*)(h + (size_t)p[g].x * 40 + lane * 4);
        }
#pragma unroll
        for (int g = 0; g < 4; g++) {
            int i = b * 4 + g;
            if (i < cnt) {
                float nm = __int_as_float(p[g].z);
                m[g].x *= nm; m[g].y *= nm; m[g].z *= nm; m[g].w *= nm;
            }
        }
#pragma unroll
        for (int g = 0; g < 4; g++) {
            int i = b * 4 + g;
            if (i < cnt) {
                if (i == 0) {
                    acc = m[0];
                    d = p[0].y;
                } else if (p[g].y == d) {
                    acc.x += m[g].x; acc.y += m[g].y;
                    acc.z += m[g].z; acc.w += m[g].w;
                } else {
                    if (act)
                        red4(out + (size_t)d * 40 + lane * 4, acc.x, acc.y, acc.z, acc.w);
                    acc = m[g];
                    d = p[g].y;
                }
            }
        }
    }
    if (act)
        red4(out + (size_t)d * 40 + lane * 4, acc.x, acc.y, acc.z, acc.w);
}

// ---------------------------------------------------------------------------
// Launch: gemm1 overlaps the graph preamble on a second stream (round-9 shape).
// ---------------------------------------------------------------------------
extern "C" void kernel_launch(void* const* d_in, const int* in_sizes, int n_in,
                              void* d_out, int out_size) {
    const float* x  = (const float*)d_in[0];
    const int*   ei = (const int*)d_in[1];
    const float* ew = (const float*)d_in[2];
    const float* W1 = (const float*)d_in[3];
    const float* b1 = (const float*)d_in[4];
    const float* W2 = (const float*)d_in[5];
    const float* b2 = (const float*)d_in[6];
    const float* W3 = (const float*)d_in[7];
    const float* b3 = (const float*)d_in[8];
    float* out = (float*)d_out;

    const int n = in_sizes[0] / 128;       // 50000
    const int e = in_sizes[2];             // 640000
    const int* src = ei;
    const int* dst = ei + e;

    int *count, *cursor, *part;
    int4* pack;
    float *dinv, *h, *agg1, *agg2, *h3;
    cudaGetSymbolAddress((void**)&count,  g_count);
    cudaGetSymbolAddress((void**)&dinv,   g_dinv);
    cudaGetSymbolAddress((void**)&part,   g_part);
    cudaGetSymbolAddress((void**)&cursor, g_cursor);
    cudaGetSymbolAddress((void**)&pack,   g_pack);
    cudaGetSymbolAddress((void**)&h,      g_h);
    cudaGetSymbolAddress((void**)&agg1,   g_agg1);
    cudaGetSymbolAddress((void**)&agg2,   g_agg2);
    cudaGetSymbolAddress((void**)&h3,     g_h3);

    static cudaStream_t s2 = nullptr;
    static cudaEvent_t evFork = nullptr, evG1 = nullptr;
    if (s2 == nullptr) {
        cudaStreamCreateWithFlags(&s2, cudaStreamNonBlocking);
        cudaEventCreateWithFlags(&evFork, cudaEventDisableTiming);
        cudaEventCreateWithFlags(&evG1, cudaEventDisableTiming);
    }

    const int nb_n = (n + 255) / 256;
    const int nb_e = (e + 255) / 256;
    const int nb_scan = (n + SCAN_CHUNK - 1) / SCAN_CHUNK;   // 49
    const int gemm_blocks = (n + 127) / 128;
    const int nw = (e + GRP - 1) / GRP;
    const int scat_blocks = (nw * 32 + 255) / 256;

    // Fork: gemm1 (graph-independent, H only) on s2
    cudaEventRecord(evFork, 0);
    cudaStreamWaitEvent(s2, evFork, 0);
    gemm128_kernel<false, false><<<gemm_blocks, 256, 0, s2>>>(
        x, W1, nullptr, nullptr, h, nullptr, n);
    cudaEventRecord(evG1, s2);

    // Preamble on main stream (concurrent with gemm1)
    zero_kernel<<<nb_n, 256>>>(count, dinv, n);
    hist_kernel<<<nb_e, 256>>>(dst, ew, count, dinv, e);
    partial_kernel<<<nb_scan, 256>>>(count, part, n);
    scanpart_kernel<<<1, 256>>>(part, nb_scan);
    scanfinal_kernel<<<nb_scan, 256>>>(count, part, dinv, cursor, n);
    fill_kernel<<<nb_e, 256>>>(src, dst, ew, dinv, cursor, pack, e);

    // Join, then layer-1 epilogue + scatter
    cudaStreamWaitEvent(0, evG1, 0);
    agg_init128<<<(n * 32 + 255) / 256, 256>>>(h, dinv, b1, agg1, n);
    scatter128_perm<<<scat_blocks, 256>>>(h, pack, agg1, e, nw);

    // Layer 2 (relu + fused epilogue)
    gemm128_kernel<true, true><<<gemm_blocks, 256>>>(agg1, W2, b2, dinv, h, agg2, n);
    scatter128_perm<<<scat_blocks, 256>>>(h, pack, agg2, e, nw);

    // Layer 3 (relu fused; scatter straight to d_out)
    static const int g40_smem = (64 * 129 + 128 * 40) * sizeof(float);
    cudaFuncSetAttribute(gemm40_kernel,
                         cudaFuncAttributeMaxDynamicSharedMemorySize, g40_smem);
    gemm40_kernel<<<(n + 63) / 64, 128, g40_smem>>>(agg2, W3, b3, dinv, h3, out, n);
    scatter40_perm<<<scat_blocks, 256>>>(h3, pack, out, e, nw);
}

// round 15
// speedup vs baseline: 1.3675x; 1.0084x over previous
#include <cuda_runtime.h>

// Problem constants (fixed by the dataset)
#define NMAX 50000
#define EMAX 640000
#define GRP 16
#define PERM 1000003LL   // prime > group count -> bijective permutation
#define SCAN_CHUNK 1024

// Scratch (allocation-free rule: __device__ globals)
__device__ int   g_count[NMAX];
__device__ float g_dinv[NMAX];
__device__ int   g_part[256];
__device__ int   g_cursor[NMAX];
__device__ int4  g_pack[EMAX];          // {src, dst, norm_bits, 0}, dst-sorted
__device__ float g_h[NMAX * 128];
__device__ float g_agg1[NMAX * 128];
__device__ float g_agg2[NMAX * 128];
__device__ float g_h3[NMAX * 40];

__device__ __forceinline__ void red4(float* p, float a, float b, float c, float d) {
    asm volatile("red.global.add.v4.f32 [%0], {%1, %2, %3, %4};"
                 :: "l"(p), "f"(a), "f"(b), "f"(c), "f"(d) : "memory");
}

// ---------------------------------------------------------------------------
// Preamble
// ---------------------------------------------------------------------------
__global__ void zero_kernel(int* count, float* deg, int n) {
    int i = blockIdx.x * blockDim.x + threadIdx.x;
    if (i < n) { count[i] = 0; deg[i] = 1.0f; }
}

__global__ void hist_kernel(const int* __restrict__ dst,
                            const float* __restrict__ ew,
                            int* __restrict__ count,
                            float* __restrict__ deg, int e) {
    int i = blockIdx.x * blockDim.x + threadIdx.x;
    if (i < e) {
        int d = dst[i];
        atomicAdd(count + d, 1);
        atomicAdd(deg + d, ew[i]);
    }
}

__global__ void __launch_bounds__(256)
partial_kernel(const int* __restrict__ count, int* __restrict__ part, int n) {
    const int t = threadIdx.x;
    const int base = blockIdx.x * SCAN_CHUNK + t * 4;
    int s = 0;
#pragma unroll
    for (int i = 0; i < 4; i++) {
        int idx = base + i;
        if (idx < n) s += count[idx];
    }
#pragma unroll
    for (int o = 16; o; o >>= 1) s += __shfl_down_sync(~0u, s, o);
    __shared__ int wsum[8];
    if ((t & 31) == 0) wsum[t >> 5] = s;
    __syncthreads();
    if (t == 0) {
        int v = 0;
#pragma unroll
        for (int i = 0; i < 8; i++) v += wsum[i];
        part[blockIdx.x] = v;
    }
}

__global__ void __launch_bounds__(256)
scanpart_kernel(int* __restrict__ part, int nb) {
    __shared__ int sh[256];
    const int t = threadIdx.x;
    int orig = (t < nb) ? part[t] : 0;
    sh[t] = orig;
    __syncthreads();
    for (int off = 1; off < 256; off <<= 1) {
        int v = (t >= off) ? sh[t - off] : 0;
        __syncthreads();
        sh[t] += v;
        __syncthreads();
    }
    if (t < nb) part[t] = sh[t] - orig;
}

__global__ void __launch_bounds__(256)
scanfinal_kernel(const int* __restrict__ count,
                 const int* __restrict__ part,
                 float* __restrict__ deg_dinv,
                 int* __restrict__ cursor, int n) {
    const int t = threadIdx.x;
    const int base = blockIdx.x * SCAN_CHUNK + t * 4;
    int c[4];
    int s = 0;
#pragma unroll
    for (int i = 0; i < 4; i++) {
        int idx = base + i;
        c[i] = (idx < n) ? count[idx] : 0;
        s += c[i];
    }
    int inc = s;
#pragma unroll
    for (int o = 1; o < 32; o <<= 1) {
        int v = __shfl_up_sync(~0u, inc, o);
        if ((t & 31) >= o) inc += v;
    }
    __shared__ int wtot[8], woff[8];
    if ((t & 31) == 31) wtot[t >> 5] = inc;
    __syncthreads();
    if (t == 0) {
        int run = 0;
#pragma unroll
        for (int i = 0; i < 8; i++) { woff[i] = run; run += wtot[i]; }
    }
    __syncthreads();
    int run = inc - s + woff[t >> 5] + part[blockIdx.x];
#pragma unroll
    for (int i = 0; i < 4; i++) {
        int idx = base + i;
        if (idx < n) {
            cursor[idx] = run;
            run += c[i];
            deg_dinv[idx] = rsqrtf(deg_dinv[idx]);
        }
    }
}

__global__ void fill_kernel(const int* __restrict__ src,
                            const int* __restrict__ dst,
                            const float* __restrict__ ew,
                            const float* __restrict__ dinv,
                            int* __restrict__ cursor,
                            int4* __restrict__ pack, int e) {
    int i = blockIdx.x * blockDim.x + threadIdx.x;
    if (i >= e) return;
    int s = src[i];
    int d = dst[i];
    int pos = atomicAdd(cursor + d, 1);
    int4 p;
    p.x = s;
    p.y = d;
    p.z = __float_as_int(dinv[s] * ew[i] * dinv[d]);
    p.w = 0;
    pack[pos] = p;
}

// agg = h*dinv^2 + bias (layer-1 epilogue)
__global__ void agg_init128(const float* __restrict__ h,
                            const float* __restrict__ dinv,
                            const float* __restrict__ bias,
                            float* __restrict__ agg, int n) {
    int idx = blockIdx.x * blockDim.x + threadIdx.x;
    if (idx >= n * 32) return;
    int row = idx >> 5;
    int c = idx & 31;
    float di = dinv[row];
    di *= di;
    float4 hv = ((const float4*)h)[idx];
    float4 bv = ((const float4*)bias)[c];
    ((float4*)agg)[idx] = make_float4(fmaf(hv.x, di, bv.x), fmaf(hv.y, di, bv.y),
                                      fmaf(hv.z, di, bv.z), fmaf(hv.w, di, bv.w));
}

// ---------------------------------------------------------------------------
// GEMM: [n,128] @ [128,128]. FUSE_EPI: also write Agg = H*dinv^2 + bias.
// (proven kernel, at the FFMA issue floor)
// ---------------------------------------------------------------------------
template <bool RELU_IN, bool FUSE_EPI>
__global__ void __launch_bounds__(256, 2)
gemm128_kernel(const float* __restrict__ A,
               const float* __restrict__ W,
               const float* __restrict__ bias,
               const float* __restrict__ dinv,
               float* __restrict__ Hout,
               float* __restrict__ AggOut,
               int n) {
    __shared__ float As[16][128];
    __shared__ float Bs[16][128];

    const int tid = threadIdx.x;
    const int tx = tid & 15;
    const int ty = tid >> 4;
    const int rb = blockIdx.x * 128;

    float acc[8][8];
#pragma unroll
    for (int i = 0; i < 8; i++)
#pragma unroll
        for (int j = 0; j < 8; j++) acc[i][j] = 0.0f;

    for (int k0 = 0; k0 < 128; k0 += 16) {
#pragma unroll
        for (int l = 0; l < 2; l++) {
            int f = tid + l * 256;
            int row = f >> 2;
            int c4 = (f & 3) * 4;
            float4 v = make_float4(0.f, 0.f, 0.f, 0.f);
            int gr = rb + row;
            if (gr < n) v = *(const float4*)(A + (size_t)gr * 128 + k0 + c4);
            if (RELU_IN) {
                v.x = fmaxf(v.x, 0.f); v.y = fmaxf(v.y, 0.f);
                v.z = fmaxf(v.z, 0.f); v.w = fmaxf(v.w, 0.f);
            }
            As[c4 + 0][row] = v.x;
            As[c4 + 1][row] = v.y;
            As[c4 + 2][row] = v.z;
            As[c4 + 3][row] = v.w;
        }
#pragma unroll
        for (int l = 0; l < 2; l++) {
            int f = tid + l * 256;
            int kr = f >> 5;
            int c = (f & 31) * 4;
            *(float4*)&Bs[kr][c] = *(const float4*)(W + (size_t)(k0 + kr) * 128 + c);
        }
        __syncthreads();

#pragma unroll
        for (int k = 0; k < 16; k++) {
            float4 a0 = *(const float4*)&As[k][ty * 8];
            float4 a1 = *(const float4*)&As[k][ty * 8 + 4];
            float4 b0 = *(const float4*)&Bs[k][tx * 8];
            float4 b1 = *(const float4*)&Bs[k][tx * 8 + 4];
            float a[8] = {a0.x, a0.y, a0.z, a0.w, a1.x, a1.y, a1.z, a1.w};
            float b[8] = {b0.x, b0.y, b0.z, b0.w, b1.x, b1.y, b1.z, b1.w};
#pragma unroll
            for (int i = 0; i < 8; i++)
#pragma unroll
                for (int j = 0; j < 8; j++)
                    acc[i][j] = fmaf(a[i], b[j], acc[i][j]);
        }
        __syncthreads();
    }

#pragma unroll
    for (int i = 0; i < 8; i++) {
        int row = rb + ty * 8 + i;
        if (row >= n) break;
        float sl = 0.f;
        if (FUSE_EPI) { sl = dinv[row]; sl *= sl; }
#pragma unroll
        for (int j = 0; j < 8; j += 4) {
            int col = tx * 8 + j;
            float4 hv = make_float4(acc[i][j], acc[i][j + 1], acc[i][j + 2], acc[i][j + 3]);
            *(float4*)(Hout + (size_t)row * 128 + col) = hv;
            if (FUSE_EPI) {
                float4 bv = *(const float4*)(bias + col);
                float4 av;
                av.x = fmaf(hv.x, sl, bv.x);
                av.y = fmaf(hv.y, sl, bv.y);
                av.z = fmaf(hv.z, sl, bv.z);
                av.w = fmaf(hv.w, sl, bv.w);
                *(float4*)(AggOut + (size_t)row * 128 + col) = av;
            }
        }
    }
}

// ---------------------------------------------------------------------------
// Permuted segment-combining scatter (128 feats), BATCHED (4-wide live set),
// GRP=16: same register footprint as GRP=8 (occupancy preserved), but per-warp
// overhead amortized 2x and ~30% fewer red4s (more same-dst combining).
// ---------------------------------------------------------------------------
__global__ void __launch_bounds__(256)
scatter128_perm(const float* __restrict__ h,
                const int4* __restrict__ pack,
                float* __restrict__ agg, int e, int nw) {
    int w = (blockIdx.x * blockDim.x + threadIdx.x) >> 5;
    int lane = threadIdx.x & 31;
    if (w >= nw) return;
    w = (int)(((long long)w * PERM) % nw);   // decorrelate concurrent dsts
    int base = w * GRP;
    int cnt = min(GRP, e - base);

    float4 acc = make_float4(0.f, 0.f, 0.f, 0.f);
    int d = -1;

#pragma unroll
    for (int b = 0; b < GRP / 4; b++) {
        int4 p[4];
#pragma unroll
        for (int g = 0; g < 4; g++) {
            int i = b * 4 + g;
            if (i < cnt) p[g] = pack[base + i];
        }
        float4 m[4];
#pragma unroll
        for (int g = 0; g < 4; g++) {
            int i = b * 4 + g;
            if (i < cnt)
                m[g] = *(const float4*)(h + (size_t)p[g].x * 128 + lane * 4);
        }
#pragma unroll
        for (int g = 0; g < 4; g++) {
            int i = b * 4 + g;
            if (i < cnt) {
                float nm = __int_as_float(p[g].z);
                m[g].x *= nm; m[g].y *= nm; m[g].z *= nm; m[g].w *= nm;
            }
        }
#pragma unroll
        for (int g = 0; g < 4; g++) {
            int i = b * 4 + g;
            if (i < cnt) {
                if (i == 0) {
                    acc = m[0];
                    d = p[0].y;
                } else if (p[g].y == d) {       // warp-uniform branch
                    acc.x += m[g].x; acc.y += m[g].y;
                    acc.z += m[g].z; acc.w += m[g].w;
                } else {
                    red4(agg + (size_t)d * 128 + lane * 4, acc.x, acc.y, acc.z, acc.w);
                    acc = m[g];
                    d = p[g].y;
                }
            }
        }
    }
    red4(agg + (size_t)d * 128 + lane * 4, acc.x, acc.y, acc.z, acc.w);
}

// ---------------------------------------------------------------------------
// Layer-3 GEMM: relu(A)[n,128] @ [128,40] -> H3 and Out init
// ---------------------------------------------------------------------------
__global__ void __launch_bounds__(128)
gemm40_kernel(const float* __restrict__ A,
              const float* __restrict__ W,
              const float* __restrict__ bias,
              const float* __restrict__ dinv,
              float* __restrict__ Hout,
              float* __restrict__ Out,
              int n) {
    extern __shared__ float sm[];
    float* xs = sm;                 // 64 rows, stride 129
    float* ws = sm + 64 * 129;      // 128*40 flat

    const int tid = threadIdx.x;
    const int rb = blockIdx.x * 64;

    for (int l = tid * 4; l < 128 * 40; l += 128 * 4)
        *(float4*)(ws + l) = *(const float4*)(W + l);

    for (int f = tid; f < 2048; f += 128) {
        int row = f >> 5;
        int c = (f & 31) * 4;
        float4 v = make_float4(0.f, 0.f, 0.f, 0.f);
        int gr = rb + row;
        if (gr < n) v = *(const float4*)(A + (size_t)gr * 128 + c);
        float* xr = xs + row * 129 + c;
        xr[0] = fmaxf(v.x, 0.f);
        xr[1] = fmaxf(v.y, 0.f);
        xr[2] = fmaxf(v.z, 0.f);
        xr[3] = fmaxf(v.w, 0.f);
    }
    __syncthreads();

    const int tc = tid & 7;
    const int tr = tid >> 3;
    float acc[4][5];
#pragma unroll
    for (int r = 0; r < 4; r++)
#pragma unroll
        for (int j = 0; j < 5; j++) acc[r][j] = 0.0f;

#pragma unroll 4
    for (int k = 0; k < 128; k++) {
        float w[5];
#pragma unroll
        for (int j = 0; j < 5; j++) w[j] = ws[k * 40 + tc + 8 * j];
#pragma unroll
        for (int r = 0; r < 4; r++) {
            float a = xs[(tr * 4 + r) * 129 + k];
#pragma unroll
            for (int j = 0; j < 5; j++) acc[r][j] = fmaf(a, w[j], acc[r][j]);
        }
    }

#pragma unroll
    for (int r = 0; r < 4; r++) {
        int row = rb + tr * 4 + r;
        if (row >= n) break;
        float sl = dinv[row];
        sl = sl * sl;
#pragma unroll
        for (int j = 0; j < 5; j++) {
            int c = tc + 8 * j;
            float v = acc[r][j];
            Hout[(size_t)row * 40 + c] = v;
            Out[(size_t)row * 40 + c] = fmaf(v, sl, bias[c]);
        }
    }
}

// ---------------------------------------------------------------------------
// Permuted segment-combining scatter (40 feats), BATCHED, GRP=16; lanes 0..9.
// ---------------------------------------------------------------------------
__global__ void __launch_bounds__(256)
scatter40_perm(const float* __restrict__ h,
               const int4* __restrict__ pack,
               float* __restrict__ out, int e, int nw) {
    int w = (blockIdx.x * blockDim.x + threadIdx.x) >> 5;
    int lane = threadIdx.x & 31;
    if (w >= nw) return;
    w = (int)(((long long)w * PERM) % nw);
    int base = w * GRP;
    int cnt = min(GRP, e - base);
    bool act = (lane < 10);

    float4 acc = make_float4(0.f, 0.f, 0.f, 0.f);
    int d = -1;

#pragma unroll
    for (int b = 0; b < GRP / 4; b++) {
        int4 p[4];
#pragma unroll
        for (int g = 0; g < 4; g++) {
            int i = b * 4 + g;
            if (i < cnt) p[g] = pack[base + i];
        }
        float4 m[4];
#pragma unroll
        for (int g = 0; g < 4; g++) {
            int i = b * 4 + g;
            m[g] = make_float4(0.f, 0.f, 0.f, 0.f);
            if (i < cnt && act)
                m[g] = *(const float4*)(h + (size_t)p[g].x * 40 + lane * 4);
        }
#pragma unroll
        for (int g = 0; g < 4; g++) {
            int i = b * 4 + g;
            if (i < cnt) {
                float nm = __int_as_float(p[g].z);
                m[g].x *= nm; m[g].y *= nm; m[g].z *= nm; m[g].w *= nm;
            }
        }
#pragma unroll
        for (int g = 0; g < 4; g++) {
            int i = b * 4 + g;
            if (i < cnt) {
                if (i == 0) {
                    acc = m[0];
                    d = p[0].y;
                } else if (p[g].y == d) {
                    acc.x += m[g].x; acc.y += m[g].y;
                    acc.z += m[g].z; acc.w += m[g].w;
                } else {
                    if (act)
                        red4(out + (size_t)d * 40 + lane * 4, acc.x, acc.y, acc.z, acc.w);
                    acc = m[g];
                    d = p[g].y;
                }
            }
        }
    }
    if (act)
        red4(out + (size_t)d * 40 + lane * 4, acc.x, acc.y, acc.z, acc.w);
}

// ---------------------------------------------------------------------------
// Launch: gemm1 overlaps the graph preamble on a second stream.
// ---------------------------------------------------------------------------
extern "C" void kernel_launch(void* const* d_in, const int* in_sizes, int n_in,
                              void* d_out, int out_size) {
    const float* x  = (const float*)d_in[0];
    const int*   ei = (const int*)d_in[1];
    const float* ew = (const float*)d_in[2];
    const float* W1 = (const float*)d_in[3];
    const float* b1 = (const float*)d_in[4];
    const float* W2 = (const float*)d_in[5];
    const float* b2 = (const float*)d_in[6];
    const float* W3 = (const float*)d_in[7];
    const float* b3 = (const float*)d_in[8];
    float* out = (float*)d_out;

    const int n = in_sizes[0] / 128;       // 50000
    const int e = in_sizes[2];             // 640000
    const int* src = ei;
    const int* dst = ei + e;

    int *count, *cursor, *part;
    int4* pack;
    float *dinv, *h, *agg1, *agg2, *h3;
    cudaGetSymbolAddress((void**)&count,  g_count);
    cudaGetSymbolAddress((void**)&dinv,   g_dinv);
    cudaGetSymbolAddress((void**)&part,   g_part);
    cudaGetSymbolAddress((void**)&cursor, g_cursor);
    cudaGetSymbolAddress((void**)&pack,   g_pack);
    cudaGetSymbolAddress((void**)&h,      g_h);
    cudaGetSymbolAddress((void**)&agg1,   g_agg1);
    cudaGetSymbolAddress((void**)&agg2,   g_agg2);
    cudaGetSymbolAddress((void**)&h3,     g_h3);

    static cudaStream_t s2 = nullptr;
    static cudaEvent_t evFork = nullptr, evG1 = nullptr;
    if (s2 == nullptr) {
        cudaStreamCreateWithFlags(&s2, cudaStreamNonBlocking);
        cudaEventCreateWithFlags(&evFork, cudaEventDisableTiming);
        cudaEventCreateWithFlags(&evG1, cudaEventDisableTiming);
    }

    const int nb_n = (n + 255) / 256;
    const int nb_e = (e + 255) / 256;
    const int nb_scan = (n + SCAN_CHUNK - 1) / SCAN_CHUNK;   // 49
    const int gemm_blocks = (n + 127) / 128;
    const int nw = (e + GRP - 1) / GRP;
    const int scat_blocks = (nw * 32 + 255) / 256;

    // Fork: gemm1 (graph-independent, H only) on s2
    cudaEventRecord(evFork, 0);
    cudaStreamWaitEvent(s2, evFork, 0);
    gemm128_kernel<false, false><<<gemm_blocks, 256, 0, s2>>>(
        x, W1, nullptr, nullptr, h, nullptr, n);
    cudaEventRecord(evG1, s2);

    // Preamble on main stream (concurrent with gemm1)
    zero_kernel<<<nb_n, 256>>>(count, dinv, n);
    hist_kernel<<<nb_e, 256>>>(dst, ew, count, dinv, e);
    partial_kernel<<<nb_scan, 256>>>(count, part, n);
    scanpart_kernel<<<1, 256>>>(part, nb_scan);
    scanfinal_kernel<<<nb_scan, 256>>>(count, part, dinv, cursor, n);
    fill_kernel<<<nb_e, 256>>>(src, dst, ew, dinv, cursor, pack, e);

    // Join, then layer-1 epilogue + scatter
    cudaStreamWaitEvent(0, evG1, 0);
    agg_init128<<<(n * 32 + 255) / 256, 256>>>(h, dinv, b1, agg1, n);
    scatter128_perm<<<scat_blocks, 256>>>(h, pack, agg1, e, nw);

    // Layer 2 (relu + fused epilogue)
    gemm128_kernel<true, true><<<gemm_blocks, 256>>>(agg1, W2, b2, dinv, h, agg2, n);
    scatter128_perm<<<scat_blocks, 256>>>(h, pack, agg2, e, nw);

    // Layer 3 (relu fused; scatter straight to d_out)
    static const int g40_smem = (64 * 129 + 128 * 40) * sizeof(float);
    cudaFuncSetAttribute(gemm40_kernel,
                         cudaFuncAttributeMaxDynamicSharedMemorySize, g40_smem);
    gemm40_kernel<<<(n + 63) / 64, 128, g40_smem>>>(agg2, W3, b3, dinv, h3, out, n);
    scatter40_perm<<<scat_blocks, 256>>>(h3, pack, out, e, nw);
}

// round 16
// speedup vs baseline: 1.8295x; 1.3379x over previous
#include <cuda_runtime.h>
#include <cuda_fp16.h>
#include <cstdint>

// Problem constants (fixed by the dataset)
#define NMAX 50000
#define EMAX 640000
#define GRP 16
#define PERM 1000003LL   // prime > group count -> bijective permutation
#define SCAN_CHUNK 1024

// Scratch (allocation-free rule: __device__ globals)
__device__ int      g_count[NMAX];
__device__ float    g_dinv[NMAX];
__device__ int      g_part[256];
__device__ int      g_cursor[NMAX];
__device__ int4     g_pack[EMAX];        // {src, dst, norm_bits, 0}, dst-sorted
__device__ float    g_h[NMAX * 128];
__device__ float    g_agg1[NMAX * 128];
__device__ float    g_agg2[NMAX * 128];
__device__ float    g_h3[NMAX * 40];
// fp16 W fragments: [8 kchunks][16 ntiles][32 lanes][2 regs] = 8192 uint32 each
__device__ uint32_t g_wf1[8192];
__device__ uint32_t g_wf2[8192];

__device__ __forceinline__ void red4(float* p, float a, float b, float c, float d) {
    asm volatile("red.global.add.v4.f32 [%0], {%1, %2, %3, %4};"
                 :: "l"(p), "f"(a), "f"(b), "f"(c), "f"(d) : "memory");
}

__device__ __forceinline__ void mma_fp16(float* c, const uint32_t* a, const uint32_t* b) {
    asm volatile(
        "mma.sync.aligned.m16n8k16.row.col.f32.f16.f16.f32 "
        "{%0,%1,%2,%3}, {%4,%5,%6,%7}, {%8,%9}, {%0,%1,%2,%3};"
        : "+f"(c[0]), "+f"(c[1]), "+f"(c[2]), "+f"(c[3])
        : "r"(a[0]), "r"(a[1]), "r"(a[2]), "r"(a[3]), "r"(b[0]), "r"(b[1]));
}

// ---------------------------------------------------------------------------
// Preamble
// ---------------------------------------------------------------------------
__global__ void zero_kernel(int* count, float* deg, int n) {
    int i = blockIdx.x * blockDim.x + threadIdx.x;
    if (i < n) { count[i] = 0; deg[i] = 1.0f; }
}

__global__ void hist_kernel(const int* __restrict__ dst,
                            const float* __restrict__ ew,
                            int* __restrict__ count,
                            float* __restrict__ deg, int e) {
    int i = blockIdx.x * blockDim.x + threadIdx.x;
    if (i < e) {
        int d = dst[i];
        atomicAdd(count + d, 1);
        atomicAdd(deg + d, ew[i]);
    }
}

__global__ void __launch_bounds__(256)
partial_kernel(const int* __restrict__ count, int* __restrict__ part, int n) {
    const int t = threadIdx.x;
    const int base = blockIdx.x * SCAN_CHUNK + t * 4;
    int s = 0;
#pragma unroll
    for (int i = 0; i < 4; i++) {
        int idx = base + i;
        if (idx < n) s += count[idx];
    }
#pragma unroll
    for (int o = 16; o; o >>= 1) s += __shfl_down_sync(~0u, s, o);
    __shared__ int wsum[8];
    if ((t & 31) == 0) wsum[t >> 5] = s;
    __syncthreads();
    if (t == 0) {
        int v = 0;
#pragma unroll
        for (int i = 0; i < 8; i++) v += wsum[i];
        part[blockIdx.x] = v;
    }
}

__global__ void __launch_bounds__(256)
scanpart_kernel(int* __restrict__ part, int nb) {
    __shared__ int sh[256];
    const int t = threadIdx.x;
    int orig = (t < nb) ? part[t] : 0;
    sh[t] = orig;
    __syncthreads();
    for (int off = 1; off < 256; off <<= 1) {
        int v = (t >= off) ? sh[t - off] : 0;
        __syncthreads();
        sh[t] += v;
        __syncthreads();
    }
    if (t < nb) part[t] = sh[t] - orig;
}

__global__ void __launch_bounds__(256)
scanfinal_kernel(const int* __restrict__ count,
                 const int* __restrict__ part,
                 float* __restrict__ deg_dinv,
                 int* __restrict__ cursor, int n) {
    const int t = threadIdx.x;
    const int base = blockIdx.x * SCAN_CHUNK + t * 4;
    int c[4];
    int s = 0;
#pragma unroll
    for (int i = 0; i < 4; i++) {
        int idx = base + i;
        c[i] = (idx < n) ? count[idx] : 0;
        s += c[i];
    }
    int inc = s;
#pragma unroll
    for (int o = 1; o < 32; o <<= 1) {
        int v = __shfl_up_sync(~0u, inc, o);
        if ((t & 31) >= o) inc += v;
    }
    __shared__ int wtot[8], woff[8];
    if ((t & 31) == 31) wtot[t >> 5] = inc;
    __syncthreads();
    if (t == 0) {
        int run = 0;
#pragma unroll
        for (int i = 0; i < 8; i++) { woff[i] = run; run += wtot[i]; }
    }
    __syncthreads();
    int run = inc - s + woff[t >> 5] + part[blockIdx.x];
#pragma unroll
    for (int i = 0; i < 4; i++) {
        int idx = base + i;
        if (idx < n) {
            cursor[idx] = run;
            run += c[i];
            deg_dinv[idx] = rsqrtf(deg_dinv[idx]);
        }
    }
}

__global__ void fill_kernel(const int* __restrict__ src,
                            const int* __restrict__ dst,
                            const float* __restrict__ ew,
                            const float* __restrict__ dinv,
                            int* __restrict__ cursor,
                            int4* __restrict__ pack, int e) {
    int i = blockIdx.x * blockDim.x + threadIdx.x;
    if (i >= e) return;
    int s = src[i];
    int d = dst[i];
    int pos = atomicAdd(cursor + d, 1);
    int4 p;
    p.x = s;
    p.y = d;
    p.z = __float_as_int(dinv[s] * ew[i] * dinv[d]);
    p.w = 0;
    pack[pos] = p;
}

// agg = h*dinv^2 + bias (layer-1 epilogue; runs on s2 overlapped with fill)
__global__ void agg_init128(const float* __restrict__ h,
                            const float* __restrict__ dinv,
                            const float* __restrict__ bias,
                            float* __restrict__ agg, int n) {
    int idx = blockIdx.x * blockDim.x + threadIdx.x;
    if (idx >= n * 32) return;
    int row = idx >> 5;
    int c = idx & 31;
    float di = dinv[row];
    di *= di;
    float4 hv = ((const float4*)h)[idx];
    float4 bv = ((const float4*)bias)[c];
    ((float4*)agg)[idx] = make_float4(fmaf(hv.x, di, bv.x), fmaf(hv.y, di, bv.y),
                                      fmaf(hv.z, di, bv.z), fmaf(hv.w, di, bv.w));
}

// ---------------------------------------------------------------------------
// W -> fp16 mma fragments (m16n8k16.row.col B operand).
// Per (kchunk, ntile, lane): b0 = halves (k0+(lane&3)*2, +1; n = ntile*8+lane>>2)
//                            b1 = same at k+8.
// ---------------------------------------------------------------------------
__global__ void wfrag_kernel(const float* __restrict__ W, uint32_t* __restrict__ wf) {
    int t = blockIdx.x * blockDim.x + threadIdx.x;
    if (t >= 8 * 16 * 32) return;
    int lane = t & 31;
    int ntile = (t >> 5) & 15;
    int chunk = t >> 9;
    int k = chunk * 16 + (lane & 3) * 2;
    int nn = ntile * 8 + (lane >> 2);
    __half2 b0 = __floats2half2_rn(W[k * 128 + nn], W[(k + 1) * 128 + nn]);
    __half2 b1 = __floats2half2_rn(W[(k + 8) * 128 + nn], W[(k + 9) * 128 + nn]);
    wf[t * 2 + 0] = *(uint32_t*)&b0;
    wf[t * 2 + 1] = *(uint32_t*)&b1;
}

// ---------------------------------------------------------------------------
// fp16 HMMA GEMM: [n,128] @ [128,128], single pass, fp32 accumulate.
// 256 threads = 8 warps (wm 0..1 x wn 0..3), warp tile 64x32, mma m16n8k16.
// A converted fp32->fp16 on load into smem (row stride 136 halves, pad-safe).
// ---------------------------------------------------------------------------
template <bool RELU_IN, bool FUSE_EPI>
__global__ void __launch_bounds__(256)
gemm128_hmma(const float* __restrict__ A,
             const uint32_t* __restrict__ wf,
             const float* __restrict__ bias,
             const float* __restrict__ dinv,
             float* __restrict__ Hout,
             float* __restrict__ AggOut,
             int n) {
    __shared__ __half As[128 * 136];   // 34816 B

    const int tid = threadIdx.x;
    const int lane = tid & 31;
    const int wid = tid >> 5;
    const int wm = wid >> 2;   // 0..1
    const int wn = wid & 3;    // 0..3
    const int rb = blockIdx.x * 128;

    // Load + convert A: 4096 float4 chunks, 16 per thread
#pragma unroll
    for (int it = 0; it < 16; it++) {
        int f = tid + it * 256;
        int row = f >> 5;
        int c4 = (f & 31) * 4;
        float4 v = make_float4(0.f, 0.f, 0.f, 0.f);
        int gr = rb + row;
        if (gr < n) v = *(const float4*)(A + (size_t)gr * 128 + c4);
        if (RELU_IN) {
            v.x = fmaxf(v.x, 0.f); v.y = fmaxf(v.y, 0.f);
            v.z = fmaxf(v.z, 0.f); v.w = fmaxf(v.w, 0.f);
        }
        __half2 h0 = __floats2half2_rn(v.x, v.y);
        __half2 h1 = __floats2half2_rn(v.z, v.w);
        uint2 u = make_uint2(*(uint32_t*)&h0, *(uint32_t*)&h1);
        *(uint2*)&As[row * 136 + c4] = u;
    }
    __syncthreads();

    float c[4][4][4];
#pragma unroll
    for (int mi = 0; mi < 4; mi++)
#pragma unroll
        for (int ni = 0; ni < 4; ni++)
#pragma unroll
            for (int r = 0; r < 4; r++) c[mi][ni][r] = 0.0f;

#pragma unroll
    for (int kc = 0; kc < 8; kc++) {
        // B fragments for this k-chunk (L1-resident, shared by all blocks)
        uint32_t bf[4][2];
#pragma unroll
        for (int ni = 0; ni < 4; ni++) {
            size_t idx = ((size_t)(kc * 16 + wn * 4 + ni) * 32 + lane) * 2;
            bf[ni][0] = wf[idx];
            bf[ni][1] = wf[idx + 1];
        }
        const int kk = kc * 16 + (lane & 3) * 2;
#pragma unroll
        for (int mi = 0; mi < 4; mi++) {
            int r0 = wm * 64 + mi * 16 + (lane >> 2);
            uint32_t a[4];
            a[0] = *(const uint32_t*)&As[r0 * 136 + kk];
            a[1] = *(const uint32_t*)&As[(r0 + 8) * 136 + kk];
            a[2] = *(const uint32_t*)&As[r0 * 136 + kk + 8];
            a[3] = *(const uint32_t*)&As[(r0 + 8) * 136 + kk + 8];
#pragma unroll
            for (int ni = 0; ni < 4; ni++)
                mma_fp16(c[mi][ni], a, bf[ni]);
        }
    }

    // Epilogue: D lane map -> rows lane>>2 (+8), cols (lane&3)*2 (+1)
#pragma unroll
    for (int mi = 0; mi < 4; mi++) {
        int r0 = rb + wm * 64 + mi * 16 + (lane >> 2);
        int r1 = r0 + 8;
        bool ok0 = (r0 < n), ok1 = (r1 < n);
        float sl0 = 0.f, sl1 = 0.f;
        if (FUSE_EPI) {
            if (ok0) { sl0 = dinv[r0]; sl0 *= sl0; }
            if (ok1) { sl1 = dinv[r1]; sl1 *= sl1; }
        }
#pragma unroll
        for (int ni = 0; ni < 4; ni++) {
            int col = wn * 32 + ni * 8 + (lane & 3) * 2;
            if (ok0)
                *(float2*)(Hout + (size_t)r0 * 128 + col) =
                    make_float2(c[mi][ni][0], c[mi][ni][1]);
            if (ok1)
                *(float2*)(Hout + (size_t)r1 * 128 + col) =
                    make_float2(c[mi][ni][2], c[mi][ni][3]);
            if (FUSE_EPI) {
                float2 b2 = *(const float2*)(bias + col);
                if (ok0)
                    *(float2*)(AggOut + (size_t)r0 * 128 + col) =
                        make_float2(fmaf(c[mi][ni][0], sl0, b2.x),
                                    fmaf(c[mi][ni][1], sl0, b2.y));
                if (ok1)
                    *(float2*)(AggOut + (size_t)r1 * 128 + col) =
                        make_float2(fmaf(c[mi][ni][2], sl1, b2.x),
                                    fmaf(c[mi][ni][3], sl1, b2.y));
            }
        }
    }
}

// ---------------------------------------------------------------------------
// Permuted segment-combining scatter (128 feats), BATCHED 4-wide, GRP=16.
// ---------------------------------------------------------------------------
__global__ void __launch_bounds__(256)
scatter128_perm(const float* __restrict__ h,
                const int4* __restrict__ pack,
                float* __restrict__ agg, int e, int nw) {
    int w = (blockIdx.x * blockDim.x + threadIdx.x) >> 5;
    int lane = threadIdx.x & 31;
    if (w >= nw) return;
    w = (int)(((long long)w * PERM) % nw);   // decorrelate concurrent dsts
    int base = w * GRP;
    int cnt = min(GRP, e - base);

    float4 acc = make_float4(0.f, 0.f, 0.f, 0.f);
    int d = -1;

#pragma unroll
    for (int b = 0; b < GRP / 4; b++) {
        int4 p[4];
#pragma unroll
        for (int g = 0; g < 4; g++) {
            int i = b * 4 + g;
            if (i < cnt) p[g] = pack[base + i];
        }
        float4 m[4];
#pragma unroll
        for (int g = 0; g < 4; g++) {
            int i = b * 4 + g;
            if (i < cnt)
                m[g] = *(const float4*)(h + (size_t)p[g].x * 128 + lane * 4);
        }
#pragma unroll
        for (int g = 0; g < 4; g++) {
            int i = b * 4 + g;
            if (i < cnt) {
                float nm = __int_as_float(p[g].z);
                m[g].x *= nm; m[g].y *= nm; m[g].z *= nm; m[g].w *= nm;
            }
        }
#pragma unroll
        for (int g = 0; g < 4; g++) {
            int i = b * 4 + g;
            if (i < cnt) {
                if (i == 0) {
                    acc = m[0];
                    d = p[0].y;
                } else if (p[g].y == d) {       // warp-uniform branch
                    acc.x += m[g].x; acc.y += m[g].y;
                    acc.z += m[g].z; acc.w += m[g].w;
                } else {
                    red4(agg + (size_t)d * 128 + lane * 4, acc.x, acc.y, acc.z, acc.w);
                    acc = m[g];
                    d = p[g].y;
                }
            }
        }
    }
    red4(agg + (size_t)d * 128 + lane * 4, acc.x, acc.y, acc.z, acc.w);
}

// ---------------------------------------------------------------------------
// Layer-3 GEMM: relu(A)[n,128] @ [128,40] -> H3 and Out init (fp32 SIMT)
// ---------------------------------------------------------------------------
__global__ void __launch_bounds__(128)
gemm40_kernel(const float* __restrict__ A,
              const float* __restrict__ W,
              const float* __restrict__ bias,
              const float* __restrict__ dinv,
              float* __restrict__ Hout,
              float* __restrict__ Out,
              int n) {
    extern __shared__ float sm[];
    float* xs = sm;                 // 64 rows, stride 129
    float* ws = sm + 64 * 129;      // 128*40 flat

    const int tid = threadIdx.x;
    const int rb = blockIdx.x * 64;

    for (int l = tid * 4; l < 128 * 40; l += 128 * 4)
        *(float4*)(ws + l) = *(const float4*)(W + l);

    for (int f = tid; f < 2048; f += 128) {
        int row = f >> 5;
        int c = (f & 31) * 4;
        float4 v = make_float4(0.f, 0.f, 0.f, 0.f);
        int gr = rb + row;
        if (gr < n) v = *(const float4*)(A + (size_t)gr * 128 + c);
        float* xr = xs + row * 129 + c;
        xr[0] = fmaxf(v.x, 0.f);
        xr[1] = fmaxf(v.y, 0.f);
        xr[2] = fmaxf(v.z, 0.f);
        xr[3] = fmaxf(v.w, 0.f);
    }
    __syncthreads();

    const int tc = tid & 7;
    const int tr = tid >> 3;
    float acc[4][5];
#pragma unroll
    for (int r = 0; r < 4; r++)
#pragma unroll
        for (int j = 0; j < 5; j++) acc[r][j] = 0.0f;

#pragma unroll 4
    for (int k = 0; k < 128; k++) {
        float w[5];
#pragma unroll
        for (int j = 0; j < 5; j++) w[j] = ws[k * 40 + tc + 8 * j];
#pragma unroll
        for (int r = 0; r < 4; r++) {
            float a = xs[(tr * 4 + r) * 129 + k];
#pragma unroll
            for (int j = 0; j < 5; j++) acc[r][j] = fmaf(a, w[j], acc[r][j]);
        }
    }

#pragma unroll
    for (int r = 0; r < 4; r++) {
        int row = rb + tr * 4 + r;
        if (row >= n) break;
        float sl = dinv[row];
        sl = sl * sl;
#pragma unroll
        for (int j = 0; j < 5; j++) {
            int c = tc + 8 * j;
            float v = acc[r][j];
            Hout[(size_t)row * 40 + c] = v;
            Out[(size_t)row * 40 + c] = fmaf(v, sl, bias[c]);
        }
    }
}

// ---------------------------------------------------------------------------
// Permuted segment-combining scatter (40 feats), BATCHED; lanes 0..9 active.
// ---------------------------------------------------------------------------
__global__ void __launch_bounds__(256)
scatter40_perm(const float* __restrict__ h,
               const int4* __restrict__ pack,
               float* __restrict__ out, int e, int nw) {
    int w = (blockIdx.x * blockDim.x + threadIdx.x) >> 5;
    int lane = threadIdx.x & 31;
    if (w >= nw) return;
    w = (int)(((long long)w * PERM) % nw);
    int base = w * GRP;
    int cnt = min(GRP, e - base);
    bool act = (lane < 10);

    float4 acc = make_float4(0.f, 0.f, 0.f, 0.f);
    int d = -1;

#pragma unroll
    for (int b = 0; b < GRP / 4; b++) {
        int4 p[4];
#pragma unroll
        for (int g = 0; g < 4; g++) {
            int i = b * 4 + g;
            if (i < cnt) p[g] = pack[base + i];
        }
        float4 m[4];
#pragma unroll
        for (int g = 0; g < 4; g++) {
            int i = b * 4 + g;
            m[g] = make_float4(0.f, 0.f, 0.f, 0.f);
            if (i < cnt && act)
                m[g] = *(const float4*)(h + (size_t)p[g].x * 40 + lane * 4);
        }
#pragma unroll
        for (int g = 0; g < 4; g++) {
            int i = b * 4 + g;
            if (i < cnt) {
                float nm = __int_as_float(p[g].z);
                m[g].x *= nm; m[g].y *= nm; m[g].z *= nm; m[g].w *= nm;
            }
        }
#pragma unroll
        for (int g = 0; g < 4; g++) {
            int i = b * 4 + g;
            if (i < cnt) {
                if (i == 0) {
                    acc = m[0];
                    d = p[0].y;
                } else if (p[g].y == d) {
                    acc.x += m[g].x; acc.y += m[g].y;
                    acc.z += m[g].z; acc.w += m[g].w;
                } else {
                    if (act)
                        red4(out + (size_t)d * 40 + lane * 4, acc.x, acc.y, acc.z, acc.w);
                    acc = m[g];
                    d = p[g].y;
                }
            }
        }
    }
    if (act)
        red4(out + (size_t)d * 40 + lane * 4, acc.x, acc.y, acc.z, acc.w);
}

// ---------------------------------------------------------------------------
// Launch: (wfrag1 + gemm1 + agg_init) on s2 overlap the graph preamble.
// ---------------------------------------------------------------------------
extern "C" void kernel_launch(void* const* d_in, const int* in_sizes, int n_in,
                              void* d_out, int out_size) {
    const float* x  = (const float*)d_in[0];
    const int*   ei = (const int*)d_in[1];
    const float* ew = (const float*)d_in[2];
    const float* W1 = (const float*)d_in[3];
    const float* b1 = (const float*)d_in[4];
    const float* W2 = (const float*)d_in[5];
    const float* b2 = (const float*)d_in[6];
    const float* W3 = (const float*)d_in[7];
    const float* b3 = (const float*)d_in[8];
    float* out = (float*)d_out;

    const int n = in_sizes[0] / 128;       // 50000
    const int e = in_sizes[2];             // 640000
    const int* src = ei;
    const int* dst = ei + e;

    int *count, *cursor, *part;
    int4* pack;
    float *dinv, *h, *agg1, *agg2, *h3;
    uint32_t *wf1, *wf2;
    cudaGetSymbolAddress((void**)&count,  g_count);
    cudaGetSymbolAddress((void**)&dinv,   g_dinv);
    cudaGetSymbolAddress((void**)&part,   g_part);
    cudaGetSymbolAddress((void**)&cursor, g_cursor);
    cudaGetSymbolAddress((void**)&pack,   g_pack);
    cudaGetSymbolAddress((void**)&h,      g_h);
    cudaGetSymbolAddress((void**)&agg1,   g_agg1);
    cudaGetSymbolAddress((void**)&agg2,   g_agg2);
    cudaGetSymbolAddress((void**)&h3,     g_h3);
    cudaGetSymbolAddress((void**)&wf1,    g_wf1);
    cudaGetSymbolAddress((void**)&wf2,    g_wf2);

    static cudaStream_t s2 = nullptr;
    static cudaEvent_t evFork = nullptr, evDinv = nullptr, evG1 = nullptr;
    if (s2 == nullptr) {
        cudaStreamCreateWithFlags(&s2, cudaStreamNonBlocking);
        cudaEventCreateWithFlags(&evFork, cudaEventDisableTiming);
        cudaEventCreateWithFlags(&evDinv, cudaEventDisableTiming);
        cudaEventCreateWithFlags(&evG1, cudaEventDisableTiming);
    }

    const int nb_n = (n + 255) / 256;
    const int nb_e = (e + 255) / 256;
    const int nb_scan = (n + SCAN_CHUNK - 1) / SCAN_CHUNK;   // 49
    const int gemm_blocks = (n + 127) / 128;
    const int nw = (e + GRP - 1) / GRP;
    const int scat_blocks = (nw * 32 + 255) / 256;

    // Fork: W1 fragments + gemm1 (graph-independent) on s2
    cudaEventRecord(evFork, 0);
    cudaStreamWaitEvent(s2, evFork, 0);
    wfrag_kernel<<<16, 256, 0, s2>>>(W1, wf1);
    gemm128_hmma<false, false><<<gemm_blocks, 256, 0, s2>>>(
        x, wf1, nullptr, nullptr, h, nullptr, n);

    // Preamble on main stream (concurrent with gemm1)
    zero_kernel<<<nb_n, 256>>>(count, dinv, n);
    wfrag_kernel<<<16, 256>>>(W2, wf2);
    hist_kernel<<<nb_e, 256>>>(dst, ew, count, dinv, e);
    partial_kernel<<<nb_scan, 256>>>(count, part, n);
    scanpart_kernel<<<1, 256>>>(part, nb_scan);
    scanfinal_kernel<<<nb_scan, 256>>>(count, part, dinv, cursor, n);
    cudaEventRecord(evDinv, 0);            // dinv ready
    fill_kernel<<<nb_e, 256>>>(src, dst, ew, dinv, cursor, pack, e);

    // agg_init on s2 (after gemm1 + dinv), overlapped with fill
    cudaStreamWaitEvent(s2, evDinv, 0);
    agg_init128<<<(n * 32 + 255) / 256, 256, 0, s2>>>(h, dinv, b1, agg1, n);
    cudaEventRecord(evG1, s2);

    // Join, then layer-1 scatter
    cudaStreamWaitEvent(0, evG1, 0);
    scatter128_perm<<<scat_blocks, 256>>>(h, pack, agg1, e, nw);

    // Layer 2 (relu + fused epilogue, fp16 HMMA)
    gemm128_hmma<true, true><<<gemm_blocks, 256>>>(agg1, wf2, b2, dinv, h, agg2, n);
    scatter128_perm<<<scat_blocks, 256>>>(h, pack, agg2, e, nw);

    // Layer 3 (relu fused; scatter straight to d_out)
    static const int g40_smem = (64 * 129 + 128 * 40) * sizeof(float);
    cudaFuncSetAttribute(gemm40_kernel,
                         cudaFuncAttributeMaxDynamicSharedMemorySize, g40_smem);
    gemm40_kernel<<<(n + 63) / 64, 128, g40_smem>>>(agg2, W3, b3, dinv, h3, out, n);
    scatter40_perm<<<scat_blocks, 256>>>(h3, pack, out, e, nw);
}

// round 17
// speedup vs baseline: 2.0591x; 1.1254x over previous
#include <cuda_runtime.h>
#include <cuda_fp16.h>
#include <cstdint>

// Problem constants (fixed by the dataset)
#define NMAX 50000
#define EMAX 640000
#define GRP 16
#define PERM 1000003LL   // prime > group count -> bijective permutation
#define SCAN_CHUNK 1024

// Scratch (allocation-free rule: __device__ globals)
__device__ int      g_count[NMAX];
__device__ float    g_dinv[NMAX];
__device__ int      g_part[256];
__device__ int      g_cursor[NMAX];
__device__ int4     g_pack[EMAX];        // {src, dst, norm_bits, 0}, dst-sorted
__device__ float    g_h[NMAX * 128];
__device__ float    g_agg1[NMAX * 128];
__device__ float    g_agg2[NMAX * 128];
__device__ float    g_h3[NMAX * 40];
// fp16 W fragments: [8 kchunks][16 ntiles][32 lanes][2 regs] = 8192 uint32 each
__device__ uint32_t g_wf1[8192];
__device__ uint32_t g_wf2[8192];
// W3 fragments: [8 kchunks][5 ntiles][32 lanes][2 regs] = 2560 uint32
__device__ uint32_t g_wf3[2560];

__device__ __forceinline__ void red4(float* p, float a, float b, float c, float d) {
    asm volatile("red.global.add.v4.f32 [%0], {%1, %2, %3, %4};"
                 :: "l"(p), "f"(a), "f"(b), "f"(c), "f"(d) : "memory");
}

__device__ __forceinline__ void mma_fp16(float* c, const uint32_t* a, const uint32_t* b) {
    asm volatile(
        "mma.sync.aligned.m16n8k16.row.col.f32.f16.f16.f32 "
        "{%0,%1,%2,%3}, {%4,%5,%6,%7}, {%8,%9}, {%0,%1,%2,%3};"
        : "+f"(c[0]), "+f"(c[1]), "+f"(c[2]), "+f"(c[3])
        : "r"(a[0]), "r"(a[1]), "r"(a[2]), "r"(a[3]), "r"(b[0]), "r"(b[1]));
}

// ---------------------------------------------------------------------------
// Preamble
// ---------------------------------------------------------------------------
__global__ void zero_kernel(int* count, float* deg, int n) {
    int i = blockIdx.x * blockDim.x + threadIdx.x;
    if (i < n) { count[i] = 0; deg[i] = 1.0f; }
}

__global__ void hist_kernel(const int* __restrict__ dst,
                            const float* __restrict__ ew,
                            int* __restrict__ count,
                            float* __restrict__ deg, int e) {
    int i = blockIdx.x * blockDim.x + threadIdx.x;
    if (i < e) {
        int d = dst[i];
        atomicAdd(count + d, 1);
        atomicAdd(deg + d, ew[i]);
    }
}

__global__ void __launch_bounds__(256)
partial_kernel(const int* __restrict__ count, int* __restrict__ part, int n) {
    const int t = threadIdx.x;
    const int base = blockIdx.x * SCAN_CHUNK + t * 4;
    int s = 0;
#pragma unroll
    for (int i = 0; i < 4; i++) {
        int idx = base + i;
        if (idx < n) s += count[idx];
    }
#pragma unroll
    for (int o = 16; o; o >>= 1) s += __shfl_down_sync(~0u, s, o);
    __shared__ int wsum[8];
    if ((t & 31) == 0) wsum[t >> 5] = s;
    __syncthreads();
    if (t == 0) {
        int v = 0;
#pragma unroll
        for (int i = 0; i < 8; i++) v += wsum[i];
        part[blockIdx.x] = v;
    }
}

__global__ void __launch_bounds__(256)
scanpart_kernel(int* __restrict__ part, int nb) {
    __shared__ int sh[256];
    const int t = threadIdx.x;
    int orig = (t < nb) ? part[t] : 0;
    sh[t] = orig;
    __syncthreads();
    for (int off = 1; off < 256; off <<= 1) {
        int v = (t >= off) ? sh[t - off] : 0;
        __syncthreads();
        sh[t] += v;
        __syncthreads();
    }
    if (t < nb) part[t] = sh[t] - orig;
}

__global__ void __launch_bounds__(256)
scanfinal_kernel(const int* __restrict__ count,
                 const int* __restrict__ part,
                 float* __restrict__ deg_dinv,
                 int* __restrict__ cursor, int n) {
    const int t = threadIdx.x;
    const int base = blockIdx.x * SCAN_CHUNK + t * 4;
    int c[4];
    int s = 0;
#pragma unroll
    for (int i = 0; i < 4; i++) {
        int idx = base + i;
        c[i] = (idx < n) ? count[idx] : 0;
        s += c[i];
    }
    int inc = s;
#pragma unroll
    for (int o = 1; o < 32; o <<= 1) {
        int v = __shfl_up_sync(~0u, inc, o);
        if ((t & 31) >= o) inc += v;
    }
    __shared__ int wtot[8], woff[8];
    if ((t & 31) == 31) wtot[t >> 5] = inc;
    __syncthreads();
    if (t == 0) {
        int run = 0;
#pragma unroll
        for (int i = 0; i < 8; i++) { woff[i] = run; run += wtot[i]; }
    }
    __syncthreads();
    int run = inc - s + woff[t >> 5] + part[blockIdx.x];
#pragma unroll
    for (int i = 0; i < 4; i++) {
        int idx = base + i;
        if (idx < n) {
            cursor[idx] = run;
            run += c[i];
            deg_dinv[idx] = rsqrtf(deg_dinv[idx]);
        }
    }
}

__global__ void fill_kernel(const int* __restrict__ src,
                            const int* __restrict__ dst,
                            const float* __restrict__ ew,
                            const float* __restrict__ dinv,
                            int* __restrict__ cursor,
                            int4* __restrict__ pack, int e) {
    int i = blockIdx.x * blockDim.x + threadIdx.x;
    if (i >= e) return;
    int s = src[i];
    int d = dst[i];
    int pos = atomicAdd(cursor + d, 1);
    int4 p;
    p.x = s;
    p.y = d;
    p.z = __float_as_int(dinv[s] * ew[i] * dinv[d]);
    p.w = 0;
    pack[pos] = p;
}

// agg = h*dinv^2 + bias (layer-1 epilogue; runs on s2 overlapped with fill)
__global__ void agg_init128(const float* __restrict__ h,
                            const float* __restrict__ dinv,
                            const float* __restrict__ bias,
                            float* __restrict__ agg, int n) {
    int idx = blockIdx.x * blockDim.x + threadIdx.x;
    if (idx >= n * 32) return;
    int row = idx >> 5;
    int c = idx & 31;
    float di = dinv[row];
    di *= di;
    float4 hv = ((const float4*)h)[idx];
    float4 bv = ((const float4*)bias)[c];
    ((float4*)agg)[idx] = make_float4(fmaf(hv.x, di, bv.x), fmaf(hv.y, di, bv.y),
                                      fmaf(hv.z, di, bv.z), fmaf(hv.w, di, bv.w));
}

// ---------------------------------------------------------------------------
// W -> fp16 mma fragments (m16n8k16.row.col B operand), NCOL columns.
// Per (kchunk, ntile, lane): b0 = halves (k0+(lane&3)*2, +1; n = ntile*8+lane>>2)
//                            b1 = same at k+8.
// ---------------------------------------------------------------------------
template <int NCOL>
__global__ void wfrag_kernel(const float* __restrict__ W, uint32_t* __restrict__ wf) {
    int t = blockIdx.x * blockDim.x + threadIdx.x;
    if (t >= 8 * (NCOL / 8) * 32) return;
    int lane = t & 31;
    int ntile = (t >> 5) % (NCOL / 8);
    int chunk = (t >> 5) / (NCOL / 8);
    int k = chunk * 16 + (lane & 3) * 2;
    int nn = ntile * 8 + (lane >> 2);
    __half2 b0 = __floats2half2_rn(W[k * NCOL + nn], W[(k + 1) * NCOL + nn]);
    __half2 b1 = __floats2half2_rn(W[(k + 8) * NCOL + nn], W[(k + 9) * NCOL + nn]);
    wf[t * 2 + 0] = *(uint32_t*)&b0;
    wf[t * 2 + 1] = *(uint32_t*)&b1;
}

// ---------------------------------------------------------------------------
// fp16 HMMA GEMM: [n,128] @ [128,128], single pass, fp32 accumulate.
// ---------------------------------------------------------------------------
template <bool RELU_IN, bool FUSE_EPI>
__global__ void __launch_bounds__(256)
gemm128_hmma(const float* __restrict__ A,
             const uint32_t* __restrict__ wf,
             const float* __restrict__ bias,
             const float* __restrict__ dinv,
             float* __restrict__ Hout,
             float* __restrict__ AggOut,
             int n) {
    __shared__ __half As[128 * 136];   // 34816 B

    const int tid = threadIdx.x;
    const int lane = tid & 31;
    const int wid = tid >> 5;
    const int wm = wid >> 2;   // 0..1
    const int wn = wid & 3;    // 0..3
    const int rb = blockIdx.x * 128;

#pragma unroll
    for (int it = 0; it < 16; it++) {
        int f = tid + it * 256;
        int row = f >> 5;
        int c4 = (f & 31) * 4;
        float4 v = make_float4(0.f, 0.f, 0.f, 0.f);
        int gr = rb + row;
        if (gr < n) v = *(const float4*)(A + (size_t)gr * 128 + c4);
        if (RELU_IN) {
            v.x = fmaxf(v.x, 0.f); v.y = fmaxf(v.y, 0.f);
            v.z = fmaxf(v.z, 0.f); v.w = fmaxf(v.w, 0.f);
        }
        __half2 h0 = __floats2half2_rn(v.x, v.y);
        __half2 h1 = __floats2half2_rn(v.z, v.w);
        uint2 u = make_uint2(*(uint32_t*)&h0, *(uint32_t*)&h1);
        *(uint2*)&As[row * 136 + c4] = u;
    }
    __syncthreads();

    float c[4][4][4];
#pragma unroll
    for (int mi = 0; mi < 4; mi++)
#pragma unroll
        for (int ni = 0; ni < 4; ni++)
#pragma unroll
            for (int r = 0; r < 4; r++) c[mi][ni][r] = 0.0f;

#pragma unroll
    for (int kc = 0; kc < 8; kc++) {
        uint32_t bf[4][2];
#pragma unroll
        for (int ni = 0; ni < 4; ni++) {
            size_t idx = ((size_t)(kc * 16 + wn * 4 + ni) * 32 + lane) * 2;
            bf[ni][0] = wf[idx];
            bf[ni][1] = wf[idx + 1];
        }
        const int kk = kc * 16 + (lane & 3) * 2;
#pragma unroll
        for (int mi = 0; mi < 4; mi++) {
            int r0 = wm * 64 + mi * 16 + (lane >> 2);
            uint32_t a[4];
            a[0] = *(const uint32_t*)&As[r0 * 136 + kk];
            a[1] = *(const uint32_t*)&As[(r0 + 8) * 136 + kk];
            a[2] = *(const uint32_t*)&As[r0 * 136 + kk + 8];
            a[3] = *(const uint32_t*)&As[(r0 + 8) * 136 + kk + 8];
#pragma unroll
            for (int ni = 0; ni < 4; ni++)
                mma_fp16(c[mi][ni], a, bf[ni]);
        }
    }

#pragma unroll
    for (int mi = 0; mi < 4; mi++) {
        int r0 = rb + wm * 64 + mi * 16 + (lane >> 2);
        int r1 = r0 + 8;
        bool ok0 = (r0 < n), ok1 = (r1 < n);
        float sl0 = 0.f, sl1 = 0.f;
        if (FUSE_EPI) {
            if (ok0) { sl0 = dinv[r0]; sl0 *= sl0; }
            if (ok1) { sl1 = dinv[r1]; sl1 *= sl1; }
        }
#pragma unroll
        for (int ni = 0; ni < 4; ni++) {
            int col = wn * 32 + ni * 8 + (lane & 3) * 2;
            if (ok0)
                *(float2*)(Hout + (size_t)r0 * 128 + col) =
                    make_float2(c[mi][ni][0], c[mi][ni][1]);
            if (ok1)
                *(float2*)(Hout + (size_t)r1 * 128 + col) =
                    make_float2(c[mi][ni][2], c[mi][ni][3]);
            if (FUSE_EPI) {
                float2 b2 = *(const float2*)(bias + col);
                if (ok0)
                    *(float2*)(AggOut + (size_t)r0 * 128 + col) =
                        make_float2(fmaf(c[mi][ni][0], sl0, b2.x),
                                    fmaf(c[mi][ni][1], sl0, b2.y));
                if (ok1)
                    *(float2*)(AggOut + (size_t)r1 * 128 + col) =
                        make_float2(fmaf(c[mi][ni][2], sl1, b2.x),
                                    fmaf(c[mi][ni][3], sl1, b2.y));
            }
        }
    }
}

// ---------------------------------------------------------------------------
// fp16 HMMA GEMM layer 3: relu(A)[n,128] @ [128,40] -> H3 and Out init.
// 256 threads = 8 warps; warp wid owns m-tile of 16 rows, all 5 n-tiles.
// ---------------------------------------------------------------------------
__global__ void __launch_bounds__(256)
gemm40_hmma(const float* __restrict__ A,
            const uint32_t* __restrict__ wf,
            const float* __restrict__ bias,
            const float* __restrict__ dinv,
            float* __restrict__ Hout,
            float* __restrict__ Out,
            int n) {
    __shared__ __half As[128 * 136];

    const int tid = threadIdx.x;
    const int lane = tid & 31;
    const int wm = tid >> 5;   // 0..7 m-tile
    const int rb = blockIdx.x * 128;

#pragma unroll
    for (int it = 0; it < 16; it++) {
        int f = tid + it * 256;
        int row = f >> 5;
        int c4 = (f & 31) * 4;
        float4 v = make_float4(0.f, 0.f, 0.f, 0.f);
        int gr = rb + row;
        if (gr < n) v = *(const float4*)(A + (size_t)gr * 128 + c4);
        v.x = fmaxf(v.x, 0.f); v.y = fmaxf(v.y, 0.f);
        v.z = fmaxf(v.z, 0.f); v.w = fmaxf(v.w, 0.f);
        __half2 h0 = __floats2half2_rn(v.x, v.y);
        __half2 h1 = __floats2half2_rn(v.z, v.w);
        uint2 u = make_uint2(*(uint32_t*)&h0, *(uint32_t*)&h1);
        *(uint2*)&As[row * 136 + c4] = u;
    }
    __syncthreads();

    float c[5][4];
#pragma unroll
    for (int ni = 0; ni < 5; ni++)
#pragma unroll
        for (int r = 0; r < 4; r++) c[ni][r] = 0.0f;

#pragma unroll
    for (int kc = 0; kc < 8; kc++) {
        const int kk = kc * 16 + (lane & 3) * 2;
        int r0 = wm * 16 + (lane >> 2);
        uint32_t a[4];
        a[0] = *(const uint32_t*)&As[r0 * 136 + kk];
        a[1] = *(const uint32_t*)&As[(r0 + 8) * 136 + kk];
        a[2] = *(const uint32_t*)&As[r0 * 136 + kk + 8];
        a[3] = *(const uint32_t*)&As[(r0 + 8) * 136 + kk + 8];
#pragma unroll
        for (int ni = 0; ni < 5; ni++) {
            size_t idx = ((size_t)(kc * 5 + ni) * 32 + lane) * 2;
            uint32_t bf[2] = { wf[idx], wf[idx + 1] };
            mma_fp16(c[ni], a, bf);
        }
    }

    int r0 = rb + wm * 16 + (lane >> 2);
    int r1 = r0 + 8;
    bool ok0 = (r0 < n), ok1 = (r1 < n);
    float sl0 = 0.f, sl1 = 0.f;
    if (ok0) { sl0 = dinv[r0]; sl0 *= sl0; }
    if (ok1) { sl1 = dinv[r1]; sl1 *= sl1; }
#pragma unroll
    for (int ni = 0; ni < 5; ni++) {
        int col = ni * 8 + (lane & 3) * 2;
        float2 b2 = *(const float2*)(bias + col);
        if (ok0) {
            *(float2*)(Hout + (size_t)r0 * 40 + col) =
                make_float2(c[ni][0], c[ni][1]);
            *(float2*)(Out + (size_t)r0 * 40 + col) =
                make_float2(fmaf(c[ni][0], sl0, b2.x), fmaf(c[ni][1], sl0, b2.y));
        }
        if (ok1) {
            *(float2*)(Hout + (size_t)r1 * 40 + col) =
                make_float2(c[ni][2], c[ni][3]);
            *(float2*)(Out + (size_t)r1 * 40 + col) =
                make_float2(fmaf(c[ni][2], sl1, b2.x), fmaf(c[ni][3], sl1, b2.y));
        }
    }
}

// ---------------------------------------------------------------------------
// Permuted segment-combining scatter (128 feats), BATCHED 4-wide, GRP=16.
// ---------------------------------------------------------------------------
__global__ void __launch_bounds__(256)
scatter128_perm(const float* __restrict__ h,
                const int4* __restrict__ pack,
                float* __restrict__ agg, int e, int nw) {
    int w = (blockIdx.x * blockDim.x + threadIdx.x) >> 5;
    int lane = threadIdx.x & 31;
    if (w >= nw) return;
    w = (int)(((long long)w * PERM) % nw);   // decorrelate concurrent dsts
    int base = w * GRP;
    int cnt = min(GRP, e - base);

    float4 acc = make_float4(0.f, 0.f, 0.f, 0.f);
    int d = -1;

#pragma unroll
    for (int b = 0; b < GRP / 4; b++) {
        int4 p[4];
#pragma unroll
        for (int g = 0; g < 4; g++) {
            int i = b * 4 + g;
            if (i < cnt) p[g] = pack[base + i];
        }
        float4 m[4];
#pragma unroll
        for (int g = 0; g < 4; g++) {
            int i = b * 4 + g;
            if (i < cnt)
                m[g] = *(const float4*)(h + (size_t)p[g].x * 128 + lane * 4);
        }
#pragma unroll
        for (int g = 0; g < 4; g++) {
            int i = b * 4 + g;
            if (i < cnt) {
                float nm = __int_as_float(p[g].z);
                m[g].x *= nm; m[g].y *= nm; m[g].z *= nm; m[g].w *= nm;
            }
        }
#pragma unroll
        for (int g = 0; g < 4; g++) {
            int i = b * 4 + g;
            if (i < cnt) {
                if (i == 0) {
                    acc = m[0];
                    d = p[0].y;
                } else if (p[g].y == d) {       // warp-uniform branch
                    acc.x += m[g].x; acc.y += m[g].y;
                    acc.z += m[g].z; acc.w += m[g].w;
                } else {
                    red4(agg + (size_t)d * 128 + lane * 4, acc.x, acc.y, acc.z, acc.w);
                    acc = m[g];
                    d = p[g].y;
                }
            }
        }
    }
    red4(agg + (size_t)d * 128 + lane * 4, acc.x, acc.y, acc.z, acc.w);
}

// ---------------------------------------------------------------------------
// Permuted segment-combining scatter (40 feats), BATCHED; lanes 0..9 active.
// ---------------------------------------------------------------------------
__global__ void __launch_bounds__(256)
scatter40_perm(const float* __restrict__ h,
               const int4* __restrict__ pack,
               float* __restrict__ out, int e, int nw) {
    int w = (blockIdx.x * blockDim.x + threadIdx.x) >> 5;
    int lane = threadIdx.x & 31;
    if (w >= nw) return;
    w = (int)(((long long)w * PERM) % nw);
    int base = w * GRP;
    int cnt = min(GRP, e - base);
    bool act = (lane < 10);

    float4 acc = make_float4(0.f, 0.f, 0.f, 0.f);
    int d = -1;

#pragma unroll
    for (int b = 0; b < GRP / 4; b++) {
        int4 p[4];
#pragma unroll
        for (int g = 0; g < 4; g++) {
            int i = b * 4 + g;
            if (i < cnt) p[g] = pack[base + i];
        }
        float4 m[4];
#pragma unroll
        for (int g = 0; g < 4; g++) {
            int i = b * 4 + g;
            m[g] = make_float4(0.f, 0.f, 0.f, 0.f);
            if (i < cnt && act)
                m[g] = *(const float4*)(h + (size_t)p[g].x * 40 + lane * 4);
        }
#pragma unroll
        for (int g = 0; g < 4; g++) {
            int i = b * 4 + g;
            if (i < cnt) {
                float nm = __int_as_float(p[g].z);
                m[g].x *= nm; m[g].y *= nm; m[g].z *= nm; m[g].w *= nm;
            }
        }
#pragma unroll
        for (int g = 0; g < 4; g++) {
            int i = b * 4 + g;
            if (i < cnt) {
                if (i == 0) {
                    acc = m[0];
                    d = p[0].y;
                } else if (p[g].y == d) {
                    acc.x += m[g].x; acc.y += m[g].y;
                    acc.z += m[g].z; acc.w += m[g].w;
                } else {
                    if (act)
                        red4(out + (size_t)d * 40 + lane * 4, acc.x, acc.y, acc.z, acc.w);
                    acc = m[g];
                    d = p[g].y;
                }
            }
        }
    }
    if (act)
        red4(out + (size_t)d * 40 + lane * 4, acc.x, acc.y, acc.z, acc.w);
}

// ---------------------------------------------------------------------------
// Launch: (wfrag1 + gemm1 + agg_init) on s2 overlap the graph preamble.
// ---------------------------------------------------------------------------
extern "C" void kernel_launch(void* const* d_in, const int* in_sizes, int n_in,
                              void* d_out, int out_size) {
    const float* x  = (const float*)d_in[0];
    const int*   ei = (const int*)d_in[1];
    const float* ew = (const float*)d_in[2];
    const float* W1 = (const float*)d_in[3];
    const float* b1 = (const float*)d_in[4];
    const float* W2 = (const float*)d_in[5];
    const float* b2 = (const float*)d_in[6];
    const float* W3 = (const float*)d_in[7];
    const float* b3 = (const float*)d_in[8];
    float* out = (float*)d_out;

    const int n = in_sizes[0] / 128;       // 50000
    const int e = in_sizes[2];             // 640000
    const int* src = ei;
    const int* dst = ei + e;

    int *count, *cursor, *part;
    int4* pack;
    float *dinv, *h, *agg1, *agg2, *h3;
    uint32_t *wf1, *wf2, *wf3;
    cudaGetSymbolAddress((void**)&count,  g_count);
    cudaGetSymbolAddress((void**)&dinv,   g_dinv);
    cudaGetSymbolAddress((void**)&part,   g_part);
    cudaGetSymbolAddress((void**)&cursor, g_cursor);
    cudaGetSymbolAddress((void**)&pack,   g_pack);
    cudaGetSymbolAddress((void**)&h,      g_h);
    cudaGetSymbolAddress((void**)&agg1,   g_agg1);
    cudaGetSymbolAddress((void**)&agg2,   g_agg2);
    cudaGetSymbolAddress((void**)&h3,     g_h3);
    cudaGetSymbolAddress((void**)&wf1,    g_wf1);
    cudaGetSymbolAddress((void**)&wf2,    g_wf2);
    cudaGetSymbolAddress((void**)&wf3,    g_wf3);

    static cudaStream_t s2 = nullptr;
    static cudaEvent_t evFork = nullptr, evDinv = nullptr, evG1 = nullptr;
    if (s2 == nullptr) {
        cudaStreamCreateWithFlags(&s2, cudaStreamNonBlocking);
        cudaEventCreateWithFlags(&evFork, cudaEventDisableTiming);
        cudaEventCreateWithFlags(&evDinv, cudaEventDisableTiming);
        cudaEventCreateWithFlags(&evG1, cudaEventDisableTiming);
    }

    const int nb_n = (n + 255) / 256;
    const int nb_e = (e + 255) / 256;
    const int nb_scan = (n + SCAN_CHUNK - 1) / SCAN_CHUNK;   // 49
    const int gemm_blocks = (n + 127) / 128;
    const int nw = (e + GRP - 1) / GRP;
    const int scat_blocks = (nw * 32 + 255) / 256;

    // Fork: W1 fragments + gemm1 (graph-independent) on s2
    cudaEventRecord(evFork, 0);
    cudaStreamWaitEvent(s2, evFork, 0);
    wfrag_kernel<128><<<16, 256, 0, s2>>>(W1, wf1);
    gemm128_hmma<false, false><<<gemm_blocks, 256, 0, s2>>>(
        x, wf1, nullptr, nullptr, h, nullptr, n);

    // Preamble on main stream (concurrent with gemm1)
    zero_kernel<<<nb_n, 256>>>(count, dinv, n);
    wfrag_kernel<128><<<16, 256>>>(W2, wf2);
    wfrag_kernel<40><<<5, 256>>>(W3, wf3);
    hist_kernel<<<nb_e, 256>>>(dst, ew, count, dinv, e);
    partial_kernel<<<nb_scan, 256>>>(count, part, n);
    scanpart_kernel<<<1, 256>>>(part, nb_scan);
    scanfinal_kernel<<<nb_scan, 256>>>(count, part, dinv, cursor, n);
    cudaEventRecord(evDinv, 0);            // dinv ready
    fill_kernel<<<nb_e, 256>>>(src, dst, ew, dinv, cursor, pack, e);

    // agg_init on s2 (after gemm1 + dinv), overlapped with fill
    cudaStreamWaitEvent(s2, evDinv, 0);
    agg_init128<<<(n * 32 + 255) / 256, 256, 0, s2>>>(h, dinv, b1, agg1, n);
    cudaEventRecord(evG1, s2);

    // Join, then layer-1 scatter
    cudaStreamWaitEvent(0, evG1, 0);
    scatter128_perm<<<scat_blocks, 256>>>(h, pack, agg1, e, nw);

    // Layer 2 (relu + fused epilogue, fp16 HMMA)
    gemm128_hmma<true, true><<<gemm_blocks, 256>>>(agg1, wf2, b2, dinv, h, agg2, n);
    scatter128_perm<<<scat_blocks, 256>>>(h, pack, agg2, e, nw);

    // Layer 3 (fp16 HMMA; relu fused; Out init fused; scatter to d_out)
    gemm40_hmma<<<gemm_blocks, 256>>>(agg2, wf3, b3, dinv, h3, out, n);
    scatter40_perm<<<scat_blocks, 256>>>(h3, pack, out, e, nw);
}